// round 5
// baseline (speedup 1.0000x reference)
#include <cuda_runtime.h>
#include <cuda_bf16.h>
#include <math.h>
#include <stdint.h>

#define D_MODEL 1024
#define SEQ     2048
#define NHEADS  16
#define HEADDIM 64
#define MAXB    2

// ---------------------------------------------------------------------------
// Device scratch
// ---------------------------------------------------------------------------
__device__ float g_q[MAXB * SEQ * D_MODEL];
__device__ float g_k[MAXB * SEQ * D_MODEL];
__device__ float g_v[MAXB * SEQ * D_MODEL];
__device__ float g_ctx[MAXB * SEQ * D_MODEL];
__device__ float g_attn[(size_t)MAXB * NHEADS * SEQ * SEQ];

// ---------------------------------------------------------------------------
// tf32 helpers
// ---------------------------------------------------------------------------
__device__ __forceinline__ uint32_t f2tf32(float x) {
    uint32_t r;
    asm("cvt.rna.tf32.f32 %0, %1;" : "=r"(r) : "f"(x));
    return r;
}

__device__ __forceinline__ float ex2(float x) {
    float r;
    asm("ex2.approx.f32 %0, %1;" : "=f"(r) : "f"(x));
    return r;
}

__device__ __forceinline__ void mma_tf32(float* c, const uint32_t* a, const uint32_t* b) {
    asm("mma.sync.aligned.m16n8k8.row.col.f32.tf32.tf32.f32 "
        "{%0,%1,%2,%3}, {%4,%5,%6,%7}, {%8,%9}, {%0,%1,%2,%3};"
        : "+f"(c[0]), "+f"(c[1]), "+f"(c[2]), "+f"(c[3])
        : "r"(a[0]), "r"(a[1]), "r"(a[2]), "r"(a[3]), "r"(b[0]), "r"(b[1]));
}

// ---------------------------------------------------------------------------
// Projection GEMM (unchanged from R4 — fragment-native smem)
// ---------------------------------------------------------------------------
struct GemmSmem {
    uint4 AF[8][4][33];
    uint2 BF[16][4][33];
};

__device__ __forceinline__ void gemm_body(
    GemmSmem& s, const float* __restrict__ A, const float* __restrict__ W,
    const float* __restrict__ bias, float* __restrict__ C, int m0, int n0)
{
    const int tid  = threadIdx.x;
    const int warp = tid >> 5;
    const int lane = tid & 31;
    const int g    = lane >> 2;
    const int kq   = lane & 3;
    const int wm   = warp >> 1;
    const int wn   = warp & 1;

    float acc[2][8][4] = {};

    for (int k0 = 0; k0 < D_MODEL; k0 += 32) {
        #pragma unroll
        for (int i = 0; i < 2; i++) {
            int idx = tid + i * 256;
            int rp = idx >> 3;
            int c4 = (idx & 7) * 4;
            int mt = rp >> 3;
            int r8 = rp & 7;
            const float* a0 = &A[(size_t)(m0 + mt * 16 + r8) * D_MODEL + k0 + c4];
            float4 vlo = *(const float4*)a0;
            float4 vhi = *(const float4*)(a0 + 8 * D_MODEL);
            int kb  = c4 >> 3;
            int off = ((c4 >> 2) & 1) * 2;
            uint32_t* base = (uint32_t*)&s.AF[mt][kb][r8 * 4];
            *(uint2*)&base[0 * 4 + off] = make_uint2(f2tf32(vlo.x), f2tf32(vhi.x));
            *(uint2*)&base[1 * 4 + off] = make_uint2(f2tf32(vlo.y), f2tf32(vhi.y));
            *(uint2*)&base[2 * 4 + off] = make_uint2(f2tf32(vlo.z), f2tf32(vhi.z));
            *(uint2*)&base[3 * 4 + off] = make_uint2(f2tf32(vlo.w), f2tf32(vhi.w));
        }
        #pragma unroll
        for (int i = 0; i < 2; i++) {
            int idx = tid + i * 256;
            int rp = idx >> 5;
            int c4 = (idx & 31) * 4;
            int kb = rp >> 2;
            int rq = rp & 3;
            const float* b0 = &W[(size_t)(k0 + kb * 8 + rq) * D_MODEL + n0 + c4];
            float4 vlo = *(const float4*)b0;
            float4 vhi = *(const float4*)(b0 + 4 * D_MODEL);
            int nt = c4 >> 3;
            int gb = c4 & 7;
            s.BF[nt][kb][(gb + 0) * 4 + rq] = make_uint2(f2tf32(vlo.x), f2tf32(vhi.x));
            s.BF[nt][kb][(gb + 1) * 4 + rq] = make_uint2(f2tf32(vlo.y), f2tf32(vhi.y));
            s.BF[nt][kb][(gb + 2) * 4 + rq] = make_uint2(f2tf32(vlo.z), f2tf32(vhi.z));
            s.BF[nt][kb][(gb + 3) * 4 + rq] = make_uint2(f2tf32(vlo.w), f2tf32(vhi.w));
        }
        __syncthreads();

        #pragma unroll
        for (int kb = 0; kb < 4; kb++) {
            uint4 a[2];
            a[0] = s.AF[wm * 2 + 0][kb][lane];
            a[1] = s.AF[wm * 2 + 1][kb][lane];
            uint2 b[8];
            #pragma unroll
            for (int jn = 0; jn < 8; jn++) b[jn] = s.BF[wn * 8 + jn][kb][lane];
            #pragma unroll
            for (int im = 0; im < 2; im++)
                #pragma unroll
                for (int jn = 0; jn < 8; jn++)
                    mma_tf32(acc[im][jn], (const uint32_t*)&a[im], (const uint32_t*)&b[jn]);
        }
        __syncthreads();
    }

    #pragma unroll
    for (int im = 0; im < 2; im++) {
        int mb = m0 + wm * 32 + im * 16;
        #pragma unroll
        for (int jn = 0; jn < 8; jn++) {
            int n = n0 + wn * 64 + jn * 8 + 2 * kq;
            float b0 = bias[n], b1 = bias[n + 1];
            float* p0 = &C[(size_t)(mb + g) * D_MODEL + n];
            float* p1 = &C[(size_t)(mb + g + 8) * D_MODEL + n];
            p0[0] = acc[im][jn][0] + b0; p0[1] = acc[im][jn][1] + b1;
            p1[0] = acc[im][jn][2] + b0; p1[1] = acc[im][jn][3] + b1;
        }
    }
}

__global__ void __launch_bounds__(256)
qkv_proj_tc(const float* __restrict__ A,
            const float* __restrict__ Wq, const float* __restrict__ bq,
            const float* __restrict__ Wk, const float* __restrict__ bk,
            const float* __restrict__ Wv, const float* __restrict__ bv,
            float* __restrict__ oq, float* __restrict__ ok, float* __restrict__ ov)
{
    __shared__ GemmSmem s;
    const int z = blockIdx.z;
    const float* W    = (z == 0) ? Wq : (z == 1) ? Wk : Wv;
    const float* bias = (z == 0) ? bq : (z == 1) ? bk : bv;
    float*       C    = (z == 0) ? oq : (z == 1) ? ok : ov;
    gemm_body(s, A, W, bias, C, blockIdx.y * 128, blockIdx.x * 128);
}

__global__ void __launch_bounds__(256)
gemm_bias_tc(const float* __restrict__ A, const float* __restrict__ W,
             const float* __restrict__ bias, float* __restrict__ C)
{
    __shared__ GemmSmem s;
    gemm_body(s, A, W, bias, C, blockIdx.y * 128, blockIdx.x * 128);
}

// ---------------------------------------------------------------------------
// Fused flash attention (no-max softmax; exact normalization):
// CTA = (16 query rows) x (full 2048 keys) for one (b,h).
// Keeps unnormalized p = exp(s*scale) for the whole strip in SMEM,
// accumulates l and O on the fly, then writes normalized P once + O/l.
// ---------------------------------------------------------------------------
struct FlashSmem {
    uint32_t PF[256 * 132];         // p_u fp32 bits, fragment-native, 135168 B
    uint32_t KF[16 * 8 * 33 * 2];   // K tile tf32 frags (uint2 granularity)
    uint32_t VF[8 * 16 * 33 * 2];   // V tile tf32 frags
    uint32_t QF[8 * 132];           // Q frags (uint4 granularity)
    float red[8][16];
    float invl[16];
};

// fragment word index inside one kb block (128 data words + 4 pad)
__device__ __forceinline__ int frag_word(int r, int c) {
    return (((r & 7) << 2) + (c & 3)) * 4 + ((r >> 3) & 1) + (((c >> 2) & 1) << 1);
}

__global__ void __launch_bounds__(256)
flash_attn(const float* __restrict__ qb, const float* __restrict__ kb_,
           const float* __restrict__ vb, const float* __restrict__ scale_ptr,
           float* __restrict__ attn, float* __restrict__ ctx, int write_p)
{
    extern __shared__ char smem_raw[];
    FlashSmem& sm = *(FlashSmem*)smem_raw;

    const int tid  = threadIdx.x;
    const int w    = tid >> 5;        // 0..7
    const int lane = tid & 31;
    const int g    = lane >> 2;
    const int kq   = lane & 3;

    const int bh = blockIdx.y;
    const int b  = bh >> 4;
    const int h  = bh & 15;
    const int m0 = blockIdx.x * 16;

    const float sc = scale_ptr[0] * 1.44269504088896f;  // fold log2(e)

    const float* qbase = qb  + (size_t)(b * SEQ + m0) * D_MODEL + h * HEADDIM;
    const float* kbase = kb_ + (size_t)b * SEQ * D_MODEL + h * HEADDIM;
    const float* vbase = vb  + (size_t)b * SEQ * D_MODEL + h * HEADDIM;

    // ---- Load Q strip (16 x 64) into fragment-native QF ----
    {
        int r  = tid >> 4;            // 0..15
        int c4 = (tid & 15) * 4;      // 0..60
        float4 q4 = *(const float4*)&qbase[(size_t)r * D_MODEL + c4];
        float qa[4] = {q4.x, q4.y, q4.z, q4.w};
        #pragma unroll
        for (int j = 0; j < 4; j++) {
            int c = c4 + j;
            sm.QF[(c >> 3) * 132 + frag_word(r, c)] = f2tf32(qa[j]);
        }
    }

    float acc_o[4] = {};
    float l_part[2] = {};

    for (int iter = 0; iter < SEQ / 128; iter++) {
        const int n0 = iter * 128;

        // ---- 1. load K,V tiles (128 keys x 64) into fragment layouts ----
        #pragma unroll
        for (int i = 0; i < 8; i++) {
            int slot = tid + i * 256;          // 0..2047
            int n  = slot >> 4;                // key 0..127
            int c4 = (slot & 15) * 4;          // 0..60
            float4 k4 = *(const float4*)&kbase[(size_t)(n0 + n) * D_MODEL + c4];
            float ka[4] = {k4.x, k4.y, k4.z, k4.w};
            #pragma unroll
            for (int j = 0; j < 4; j++) {
                int c = c4 + j;
                // KF[nt=n>>3][kb=c>>3][lane=(n&7)*4+(c&3)] comp (c>>2)&1
                sm.KF[((((n >> 3) * 8) + (c >> 3)) * 33 + ((n & 7) * 4 + (c & 3))) * 2
                      + ((c >> 2) & 1)] = f2tf32(ka[j]);
            }
            float4 v4 = *(const float4*)&vbase[(size_t)(n0 + n) * D_MODEL + c4];
            float va[4] = {v4.x, v4.y, v4.z, v4.w};
            #pragma unroll
            for (int j = 0; j < 4; j++) {
                int d = c4 + j;
                // VF[nt=d>>3][kb=n>>3][lane=(d&7)*4+(n&3)] comp (n>>2)&1
                sm.VF[((((d >> 3) * 16) + (n >> 3)) * 33 + ((d & 7) * 4 + (n & 3))) * 2
                      + ((n >> 2) & 1)] = f2tf32(va[j]);
            }
        }
        __syncthreads();

        // ---- 2. S = Q K^T for this warp's 16x16 sub-tile ----
        float acc[2][4] = {};
        #pragma unroll
        for (int kb = 0; kb < 8; kb++) {
            uint4 a = *(const uint4*)&sm.QF[kb * 132 + lane * 4];
            uint2 b0 = *(const uint2*)&sm.KF[(((w * 2 + 0) * 8 + kb) * 33 + lane) * 2];
            uint2 b1 = *(const uint2*)&sm.KF[(((w * 2 + 1) * 8 + kb) * 33 + lane) * 2];
            mma_tf32(acc[0], (const uint32_t*)&a, (const uint32_t*)&b0);
            mma_tf32(acc[1], (const uint32_t*)&a, (const uint32_t*)&b1);
        }

        // ---- 3. p_u = exp(s*scale); store to PF; accumulate l ----
        #pragma unroll
        for (int jn = 0; jn < 2; jn++) {
            #pragma unroll
            for (int q = 0; q < 4; q++) {
                float pu = ex2(acc[jn][q] * sc);
                int rh = q >> 1;
                int r  = (rh << 3) + g;
                int c  = w * 16 + jn * 8 + 2 * kq + (q & 1);
                sm.PF[(iter * 16 + (c >> 3)) * 132 + frag_word(r, c)] = __float_as_uint(pu);
                l_part[rh] += pu;
            }
        }
        __syncthreads();

        // ---- 4. O += P_u * V ----
        #pragma unroll
        for (int kb = 0; kb < 16; kb++) {
            uint4 praw = *(const uint4*)&sm.PF[(iter * 16 + kb) * 132 + lane * 4];
            uint32_t pa[4];
            pa[0] = f2tf32(__uint_as_float(praw.x));
            pa[1] = f2tf32(__uint_as_float(praw.y));
            pa[2] = f2tf32(__uint_as_float(praw.z));
            pa[3] = f2tf32(__uint_as_float(praw.w));
            uint2 bv2 = *(const uint2*)&sm.VF[((w * 16 + kb) * 33 + lane) * 2];
            mma_tf32(acc_o, pa, (const uint32_t*)&bv2);
        }
        __syncthreads();
    }

    // ---- l reduction: over kq lanes, then over warps ----
    #pragma unroll
    for (int q = 0; q < 2; q++) {
        l_part[q] += __shfl_xor_sync(0xffffffff, l_part[q], 1);
        l_part[q] += __shfl_xor_sync(0xffffffff, l_part[q], 2);
    }
    if (kq == 0) {
        sm.red[w][g]     = l_part[0];
        sm.red[w][g + 8] = l_part[1];
    }
    __syncthreads();
    if (tid < 16) {
        float s = 0.f;
        #pragma unroll
        for (int ww = 0; ww < 8; ww++) s += sm.red[ww][tid];
        sm.invl[tid] = 1.0f / s;
    }
    __syncthreads();

    // ---- write O = O_u / l ----
    {
        float il0 = sm.invl[g];
        float il1 = sm.invl[g + 8];
        int d = h * HEADDIM + w * 8 + 2 * kq;
        float* p0 = &ctx[(size_t)(b * SEQ + m0 + g)     * D_MODEL + d];
        float* p1 = &ctx[(size_t)(b * SEQ + m0 + g + 8) * D_MODEL + d];
        p0[0] = acc_o[0] * il0; p0[1] = acc_o[1] * il0;
        p1[0] = acc_o[2] * il1; p1[1] = acc_o[3] * il1;
    }

    // ---- write normalized P strip (coalesced) ----
    if (write_p) {
        const int r  = tid >> 4;
        const int rh = (r >> 3) & 1;
        const float il = sm.invl[r];
        float* rowp = attn + ((size_t)bh * SEQ + m0 + r) * SEQ;
        #pragma unroll 4
        for (int it = 0; it < 32; it++) {
            int c  = (tid & 15) * 4 + it * 64;
            int kb = c >> 3;
            int kh = (c >> 2) & 1;
            int wb = kb * 132 + ((r & 7) << 4) + rh + (kh << 1);
            float4 o;
            o.x = __uint_as_float(sm.PF[wb + 0])  * il;
            o.y = __uint_as_float(sm.PF[wb + 4])  * il;
            o.z = __uint_as_float(sm.PF[wb + 8])  * il;
            o.w = __uint_as_float(sm.PF[wb + 12]) * il;
            *(float4*)&rowp[c] = o;
        }
    }
}

// ---------------------------------------------------------------------------
// Launch
// ---------------------------------------------------------------------------
extern "C" void kernel_launch(void* const* d_in, const int* in_sizes, int n_in,
                              void* d_out, int out_size)
{
    const float* Q     = (const float*)d_in[0];
    const float* Wq    = (const float*)d_in[1];
    const float* bq    = (const float*)d_in[2];
    const float* Wk    = (const float*)d_in[3];
    const float* bk    = (const float*)d_in[4];
    const float* Wv    = (const float*)d_in[5];
    const float* bv    = (const float*)d_in[6];
    const float* Wo    = (const float*)d_in[7];
    const float* bo    = (const float*)d_in[8];
    const float* scale = (const float*)d_in[9];

    const int M = in_sizes[0] / D_MODEL;   // B * SEQ
    const int B = M / SEQ;

    float* out = (float*)d_out;

    float *qp, *kp, *vp, *cp, *ap;
    cudaGetSymbolAddress((void**)&qp, g_q);
    cudaGetSymbolAddress((void**)&kp, g_k);
    cudaGetSymbolAddress((void**)&vp, g_v);
    cudaGetSymbolAddress((void**)&cp, g_ctx);
    cudaGetSymbolAddress((void**)&ap, g_attn);

    const size_t out_elems = (size_t)M * D_MODEL;
    const int write_p = ((size_t)out_size > out_elems) ? 1 : 0;
    float* attn = write_p ? (out + out_elems) : ap;

    dim3 gqkv(D_MODEL / 128, M / 128, 3);
    qkv_proj_tc<<<gqkv, 256>>>(Q, Wq, bq, Wk, bk, Wv, bv, qp, kp, vp);

    const int smem_bytes = (int)sizeof(FlashSmem);
    cudaFuncSetAttribute(flash_attn, cudaFuncAttributeMaxDynamicSharedMemorySize,
                         smem_bytes);
    dim3 gfa(SEQ / 16, B * NHEADS);            // (128, 32)
    flash_attn<<<gfa, 256, smem_bytes>>>(qp, kp, vp, scale, attn, cp, write_p);

    dim3 gproj(D_MODEL / 128, M / 128);
    gemm_bias_tc<<<gproj, 256>>>(cp, Wo, bo, out);
}

// round 6
// speedup vs baseline: 2.5454x; 2.5454x over previous
#include <cuda_runtime.h>
#include <cuda_bf16.h>
#include <math.h>
#include <stdint.h>

#define D_MODEL 1024
#define SEQ     2048
#define NHEADS  16
#define HEADDIM 64
#define MAXB    2

// ---------------------------------------------------------------------------
// Device scratch
// ---------------------------------------------------------------------------
__device__ float g_q[MAXB * SEQ * D_MODEL];
__device__ float g_k[MAXB * SEQ * D_MODEL];
__device__ float g_v[MAXB * SEQ * D_MODEL];
__device__ float g_ctx[MAXB * SEQ * D_MODEL];
__device__ float g_invl[MAXB * NHEADS * SEQ];
__device__ float g_attn[(size_t)MAXB * NHEADS * SEQ * SEQ];

// ---------------------------------------------------------------------------
// tf32 helpers
// ---------------------------------------------------------------------------
__device__ __forceinline__ uint32_t f2tf32(float x) {
    uint32_t r;
    asm("cvt.rna.tf32.f32 %0, %1;" : "=r"(r) : "f"(x));
    return r;
}

__device__ __forceinline__ float ex2(float x) {
    float r;
    asm("ex2.approx.f32 %0, %1;" : "=f"(r) : "f"(x));
    return r;
}

__device__ __forceinline__ void mma_tf32(float* c, const uint32_t* a, const uint32_t* b) {
    asm("mma.sync.aligned.m16n8k8.row.col.f32.tf32.tf32.f32 "
        "{%0,%1,%2,%3}, {%4,%5,%6,%7}, {%8,%9}, {%0,%1,%2,%3};"
        : "+f"(c[0]), "+f"(c[1]), "+f"(c[2]), "+f"(c[3])
        : "r"(a[0]), "r"(a[1]), "r"(a[2]), "r"(a[3]), "r"(b[0]), "r"(b[1]));
}

// ---------------------------------------------------------------------------
// Projection GEMM (R4, fragment-native smem)
// ---------------------------------------------------------------------------
struct GemmSmem {
    uint4 AF[8][4][33];
    uint2 BF[16][4][33];
};

__device__ __forceinline__ void gemm_body(
    GemmSmem& s, const float* __restrict__ A, const float* __restrict__ W,
    const float* __restrict__ bias, float* __restrict__ C, int m0, int n0)
{
    const int tid  = threadIdx.x;
    const int warp = tid >> 5;
    const int lane = tid & 31;
    const int g    = lane >> 2;
    const int kq   = lane & 3;
    const int wm   = warp >> 1;
    const int wn   = warp & 1;

    float acc[2][8][4] = {};

    for (int k0 = 0; k0 < D_MODEL; k0 += 32) {
        #pragma unroll
        for (int i = 0; i < 2; i++) {
            int idx = tid + i * 256;
            int rp = idx >> 3;
            int c4 = (idx & 7) * 4;
            int mt = rp >> 3;
            int r8 = rp & 7;
            const float* a0 = &A[(size_t)(m0 + mt * 16 + r8) * D_MODEL + k0 + c4];
            float4 vlo = *(const float4*)a0;
            float4 vhi = *(const float4*)(a0 + 8 * D_MODEL);
            int kb  = c4 >> 3;
            int off = ((c4 >> 2) & 1) * 2;
            uint32_t* base = (uint32_t*)&s.AF[mt][kb][r8 * 4];
            *(uint2*)&base[0 * 4 + off] = make_uint2(f2tf32(vlo.x), f2tf32(vhi.x));
            *(uint2*)&base[1 * 4 + off] = make_uint2(f2tf32(vlo.y), f2tf32(vhi.y));
            *(uint2*)&base[2 * 4 + off] = make_uint2(f2tf32(vlo.z), f2tf32(vhi.z));
            *(uint2*)&base[3 * 4 + off] = make_uint2(f2tf32(vlo.w), f2tf32(vhi.w));
        }
        #pragma unroll
        for (int i = 0; i < 2; i++) {
            int idx = tid + i * 256;
            int rp = idx >> 5;
            int c4 = (idx & 31) * 4;
            int kb = rp >> 2;
            int rq = rp & 3;
            const float* b0 = &W[(size_t)(k0 + kb * 8 + rq) * D_MODEL + n0 + c4];
            float4 vlo = *(const float4*)b0;
            float4 vhi = *(const float4*)(b0 + 4 * D_MODEL);
            int nt = c4 >> 3;
            int gb = c4 & 7;
            s.BF[nt][kb][(gb + 0) * 4 + rq] = make_uint2(f2tf32(vlo.x), f2tf32(vhi.x));
            s.BF[nt][kb][(gb + 1) * 4 + rq] = make_uint2(f2tf32(vlo.y), f2tf32(vhi.y));
            s.BF[nt][kb][(gb + 2) * 4 + rq] = make_uint2(f2tf32(vlo.z), f2tf32(vhi.z));
            s.BF[nt][kb][(gb + 3) * 4 + rq] = make_uint2(f2tf32(vlo.w), f2tf32(vhi.w));
        }
        __syncthreads();

        #pragma unroll
        for (int kb = 0; kb < 4; kb++) {
            uint4 a[2];
            a[0] = s.AF[wm * 2 + 0][kb][lane];
            a[1] = s.AF[wm * 2 + 1][kb][lane];
            uint2 b[8];
            #pragma unroll
            for (int jn = 0; jn < 8; jn++) b[jn] = s.BF[wn * 8 + jn][kb][lane];
            #pragma unroll
            for (int im = 0; im < 2; im++)
                #pragma unroll
                for (int jn = 0; jn < 8; jn++)
                    mma_tf32(acc[im][jn], (const uint32_t*)&a[im], (const uint32_t*)&b[jn]);
        }
        __syncthreads();
    }

    #pragma unroll
    for (int im = 0; im < 2; im++) {
        int mb = m0 + wm * 32 + im * 16;
        #pragma unroll
        for (int jn = 0; jn < 8; jn++) {
            int n = n0 + wn * 64 + jn * 8 + 2 * kq;
            float b0 = bias[n], b1 = bias[n + 1];
            float* p0 = &C[(size_t)(mb + g) * D_MODEL + n];
            float* p1 = &C[(size_t)(mb + g + 8) * D_MODEL + n];
            p0[0] = acc[im][jn][0] + b0; p0[1] = acc[im][jn][1] + b1;
            p1[0] = acc[im][jn][2] + b0; p1[1] = acc[im][jn][3] + b1;
        }
    }
}

__global__ void __launch_bounds__(256)
qkv_proj_tc(const float* __restrict__ A,
            const float* __restrict__ Wq, const float* __restrict__ bq,
            const float* __restrict__ Wk, const float* __restrict__ bk,
            const float* __restrict__ Wv, const float* __restrict__ bv,
            float* __restrict__ oq, float* __restrict__ ok, float* __restrict__ ov)
{
    __shared__ GemmSmem s;
    const int z = blockIdx.z;
    const float* W    = (z == 0) ? Wq : (z == 1) ? Wk : Wv;
    const float* bias = (z == 0) ? bq : (z == 1) ? bk : bv;
    float*       C    = (z == 0) ? oq : (z == 1) ? ok : ov;
    gemm_body(s, A, W, bias, C, blockIdx.y * 128, blockIdx.x * 128);
}

__global__ void __launch_bounds__(256)
gemm_bias_tc(const float* __restrict__ A, const float* __restrict__ W,
             const float* __restrict__ bias, float* __restrict__ C)
{
    __shared__ GemmSmem s;
    gemm_body(s, A, W, bias, C, blockIdx.y * 128, blockIdx.x * 128);
}

// ---------------------------------------------------------------------------
// scores+exp fused: CTA owns a 128-row strip x all 2048 keys of one (b,h).
// Writes P_u = exp(scale * QK^T) and invl = 1/rowsum(P_u).
// ---------------------------------------------------------------------------
struct ScoresSmem {
    uint4 QF[8][8][33];    // Q strip 128 x 64, fragment-native
    uint2 KF[16][8][33];   // K tile 128(keys) x 64(k)
    float red[2][128];
};

__global__ void __launch_bounds__(256)
scores_exp_tc(const float* __restrict__ qb, const float* __restrict__ kb_,
              const float* __restrict__ scale_ptr, float* __restrict__ attn,
              float* __restrict__ invl_out)
{
    extern __shared__ char smem_raw[];
    ScoresSmem& sm = *(ScoresSmem*)smem_raw;

    const int tid  = threadIdx.x;
    const int warp = tid >> 5;
    const int lane = tid & 31;
    const int g    = lane >> 2;
    const int kq   = lane & 3;
    const int wm   = warp >> 1;
    const int wn   = warp & 1;

    const int bh = blockIdx.y;
    const int b  = bh >> 4;
    const int h  = bh & 15;
    const int m0 = blockIdx.x * 128;

    const float sc = scale_ptr[0] * 1.44269504088896f;   // fold log2(e)

    const float* qbase = qb  + (size_t)(b * SEQ + m0) * D_MODEL + h * HEADDIM;
    const float* kbase = kb_ + (size_t)b * SEQ * D_MODEL + h * HEADDIM;
    float* pstrip = attn + ((size_t)bh * SEQ + m0) * SEQ;

    // ---- Q strip 128x64 -> QF (once) ----
    #pragma unroll
    for (int k0 = 0; k0 < 64; k0 += 32) {
        #pragma unroll
        for (int i = 0; i < 2; i++) {
            int idx = tid + i * 256;
            int rp = idx >> 3;
            int c4 = (idx & 7) * 4;
            int mt = rp >> 3;
            int r8 = rp & 7;
            const float* a0 = &qbase[(size_t)(mt * 16 + r8) * D_MODEL + k0 + c4];
            float4 vlo = *(const float4*)a0;
            float4 vhi = *(const float4*)(a0 + 8 * D_MODEL);
            int kb  = (k0 + c4) >> 3;
            int off = ((c4 >> 2) & 1) * 2;
            uint32_t* base = (uint32_t*)&sm.QF[mt][kb][r8 * 4];
            *(uint2*)&base[0 * 4 + off] = make_uint2(f2tf32(vlo.x), f2tf32(vhi.x));
            *(uint2*)&base[1 * 4 + off] = make_uint2(f2tf32(vlo.y), f2tf32(vhi.y));
            *(uint2*)&base[2 * 4 + off] = make_uint2(f2tf32(vlo.z), f2tf32(vhi.z));
            *(uint2*)&base[3 * 4 + off] = make_uint2(f2tf32(vlo.w), f2tf32(vhi.w));
        }
    }

    float l_acc[2][2] = {};   // [im][rh]

    for (int iter = 0; iter < SEQ / 128; iter++) {
        const int n0 = iter * 128;

        // ---- K tile 128 keys x 64 -> KF ----
        #pragma unroll
        for (int i = 0; i < 4; i++) {
            int idx = tid + i * 256;          // 1024 slots: 128 keys x 8 col-groups
            int n  = idx >> 3;                // 0..127
            int c8 = (idx & 7) * 8;           // 0..56
            const float* p = &kbase[(size_t)(n0 + n) * D_MODEL + c8];
            float4 vlo = *(const float4*)p;
            float4 vhi = *(const float4*)(p + 4);
            int nt  = n >> 3;
            int gg  = n & 7;
            int kbk = c8 >> 3;
            sm.KF[nt][kbk][gg * 4 + 0] = make_uint2(f2tf32(vlo.x), f2tf32(vhi.x));
            sm.KF[nt][kbk][gg * 4 + 1] = make_uint2(f2tf32(vlo.y), f2tf32(vhi.y));
            sm.KF[nt][kbk][gg * 4 + 2] = make_uint2(f2tf32(vlo.z), f2tf32(vhi.z));
            sm.KF[nt][kbk][gg * 4 + 3] = make_uint2(f2tf32(vlo.w), f2tf32(vhi.w));
        }
        __syncthreads();

        // ---- S tile 128x128 ----
        float acc[2][8][4] = {};
        #pragma unroll
        for (int kb = 0; kb < 8; kb++) {
            uint4 a[2];
            a[0] = sm.QF[wm * 2 + 0][kb][lane];
            a[1] = sm.QF[wm * 2 + 1][kb][lane];
            uint2 bfr[8];
            #pragma unroll
            for (int jn = 0; jn < 8; jn++) bfr[jn] = sm.KF[wn * 8 + jn][kb][lane];
            #pragma unroll
            for (int im = 0; im < 2; im++)
                #pragma unroll
                for (int jn = 0; jn < 8; jn++)
                    mma_tf32(acc[im][jn], (const uint32_t*)&a[im], (const uint32_t*)&bfr[jn]);
        }

        // ---- exp epilogue: write P_u, accumulate row sums ----
        #pragma unroll
        for (int im = 0; im < 2; im++) {
            int mb = wm * 32 + im * 16;
            #pragma unroll
            for (int jn = 0; jn < 8; jn++) {
                int n = n0 + wn * 64 + jn * 8 + 2 * kq;
                float pu0 = ex2(acc[im][jn][0] * sc);
                float pu1 = ex2(acc[im][jn][1] * sc);
                float pu2 = ex2(acc[im][jn][2] * sc);
                float pu3 = ex2(acc[im][jn][3] * sc);
                l_acc[im][0] += pu0 + pu1;
                l_acc[im][1] += pu2 + pu3;
                *(float2*)&pstrip[(size_t)(mb + g) * SEQ + n]     = make_float2(pu0, pu1);
                *(float2*)&pstrip[(size_t)(mb + g + 8) * SEQ + n] = make_float2(pu2, pu3);
            }
        }
        __syncthreads();
    }

    // ---- row-sum reduction -> invl ----
    #pragma unroll
    for (int im = 0; im < 2; im++)
        #pragma unroll
        for (int rh = 0; rh < 2; rh++) {
            l_acc[im][rh] += __shfl_xor_sync(0xffffffff, l_acc[im][rh], 1);
            l_acc[im][rh] += __shfl_xor_sync(0xffffffff, l_acc[im][rh], 2);
        }
    if (kq == 0) {
        #pragma unroll
        for (int im = 0; im < 2; im++)
            #pragma unroll
            for (int rh = 0; rh < 2; rh++)
                sm.red[wn][wm * 32 + im * 16 + rh * 8 + g] = l_acc[im][rh];
    }
    __syncthreads();
    if (tid < 128) {
        float l = sm.red[0][tid] + sm.red[1][tid];
        invl_out[(size_t)bh * SEQ + m0 + tid] = 1.0f / l;
    }
}

// ---------------------------------------------------------------------------
// PV + normalization: O = (P_u @ V) * invl; also rewrites P = P_u * invl
// in place during the load phase. Tile 128x64, BK=32.
// ---------------------------------------------------------------------------
__global__ void __launch_bounds__(256)
pv_norm_tc(float* attn, const float* __restrict__ vb,
           const float* __restrict__ invl_in, float* __restrict__ ctx, int write_p)
{
    __shared__ uint4 PF[8][4][33];
    __shared__ uint2 VF[8][4][33];
    __shared__ float sinvl[128];

    const int tid  = threadIdx.x;
    const int warp = tid >> 5;
    const int lane = tid & 31;
    const int g    = lane >> 2;
    const int kq   = lane & 3;
    const int wm   = warp >> 1;
    const int wn   = warp & 1;

    const int bh = blockIdx.z;
    const int b  = bh >> 4;
    const int h  = bh & 15;
    const int m0 = blockIdx.x * 128;

    float* pbase = attn + ((size_t)bh * SEQ + m0) * SEQ;
    const float* vbase = vb + (size_t)b * SEQ * D_MODEL + h * HEADDIM;

    if (tid < 128) sinvl[tid] = invl_in[(size_t)bh * SEQ + m0 + tid];
    __syncthreads();

    float acc[2][4][4] = {};

    for (int k0 = 0; k0 < SEQ; k0 += 32) {
        // P tile 128x32 -> PF (+ normalized rewrite)
        #pragma unroll
        for (int i = 0; i < 2; i++) {
            int idx = tid + i * 256;
            int rp = idx >> 3;
            int c4 = (idx & 7) * 4;
            int mt = rp >> 3;
            int r8 = rp & 7;
            float* a0 = &pbase[(size_t)(mt * 16 + r8) * SEQ + k0 + c4];
            float4 vlo = *(const float4*)a0;
            float4 vhi = *(const float4*)(a0 + 8 * SEQ);
            if (write_p) {
                float il0 = sinvl[mt * 16 + r8];
                float il1 = sinvl[mt * 16 + r8 + 8];
                *(float4*)a0 = make_float4(vlo.x * il0, vlo.y * il0, vlo.z * il0, vlo.w * il0);
                *(float4*)(a0 + 8 * SEQ) = make_float4(vhi.x * il1, vhi.y * il1, vhi.z * il1, vhi.w * il1);
            }
            int kbk = c4 >> 3;
            int off = ((c4 >> 2) & 1) * 2;
            uint32_t* base = (uint32_t*)&PF[mt][kbk][r8 * 4];
            *(uint2*)&base[0 * 4 + off] = make_uint2(f2tf32(vlo.x), f2tf32(vhi.x));
            *(uint2*)&base[1 * 4 + off] = make_uint2(f2tf32(vlo.y), f2tf32(vhi.y));
            *(uint2*)&base[2 * 4 + off] = make_uint2(f2tf32(vlo.z), f2tf32(vhi.z));
            *(uint2*)&base[3 * 4 + off] = make_uint2(f2tf32(vlo.w), f2tf32(vhi.w));
        }
        // V tile 32(k) x 64(n) -> VF
        {
            int rp = tid >> 4;
            int c4 = (tid & 15) * 4;
            int kbk = rp >> 2;
            int rq  = rp & 3;
            const float* v0 = &vbase[(size_t)(k0 + kbk * 8 + rq) * D_MODEL + c4];
            float4 vlo = *(const float4*)v0;
            float4 vhi = *(const float4*)(v0 + 4 * D_MODEL);
            int nt = c4 >> 3;
            int gb = c4 & 7;
            VF[nt][kbk][(gb + 0) * 4 + rq] = make_uint2(f2tf32(vlo.x), f2tf32(vhi.x));
            VF[nt][kbk][(gb + 1) * 4 + rq] = make_uint2(f2tf32(vlo.y), f2tf32(vhi.y));
            VF[nt][kbk][(gb + 2) * 4 + rq] = make_uint2(f2tf32(vlo.z), f2tf32(vhi.z));
            VF[nt][kbk][(gb + 3) * 4 + rq] = make_uint2(f2tf32(vlo.w), f2tf32(vhi.w));
        }
        __syncthreads();

        #pragma unroll
        for (int kbk = 0; kbk < 4; kbk++) {
            uint4 a[2];
            a[0] = PF[wm * 2 + 0][kbk][lane];
            a[1] = PF[wm * 2 + 1][kbk][lane];
            uint2 bfr[4];
            #pragma unroll
            for (int jn = 0; jn < 4; jn++) bfr[jn] = VF[wn * 4 + jn][kbk][lane];
            #pragma unroll
            for (int im = 0; im < 2; im++)
                #pragma unroll
                for (int jn = 0; jn < 4; jn++)
                    mma_tf32(acc[im][jn], (const uint32_t*)&a[im], (const uint32_t*)&bfr[jn]);
        }
        __syncthreads();
    }

    #pragma unroll
    for (int im = 0; im < 2; im++) {
        int mr = wm * 32 + im * 16;
        float il0 = sinvl[mr + g];
        float il1 = sinvl[mr + g + 8];
        int mb = b * SEQ + m0 + mr;
        #pragma unroll
        for (int jn = 0; jn < 4; jn++) {
            int n = h * HEADDIM + wn * 32 + jn * 8 + 2 * kq;
            float* p0 = &ctx[(size_t)(mb + g) * D_MODEL + n];
            float* p1 = &ctx[(size_t)(mb + g + 8) * D_MODEL + n];
            p0[0] = acc[im][jn][0] * il0; p0[1] = acc[im][jn][1] * il0;
            p1[0] = acc[im][jn][2] * il1; p1[1] = acc[im][jn][3] * il1;
        }
    }
}

// ---------------------------------------------------------------------------
// Launch
// ---------------------------------------------------------------------------
extern "C" void kernel_launch(void* const* d_in, const int* in_sizes, int n_in,
                              void* d_out, int out_size)
{
    const float* Q     = (const float*)d_in[0];
    const float* Wq    = (const float*)d_in[1];
    const float* bq    = (const float*)d_in[2];
    const float* Wk    = (const float*)d_in[3];
    const float* bk    = (const float*)d_in[4];
    const float* Wv    = (const float*)d_in[5];
    const float* bv    = (const float*)d_in[6];
    const float* Wo    = (const float*)d_in[7];
    const float* bo    = (const float*)d_in[8];
    const float* scale = (const float*)d_in[9];

    const int M = in_sizes[0] / D_MODEL;   // B * SEQ
    const int B = M / SEQ;

    float* out = (float*)d_out;

    float *qp, *kp, *vp, *cp, *ap, *ilp;
    cudaGetSymbolAddress((void**)&qp, g_q);
    cudaGetSymbolAddress((void**)&kp, g_k);
    cudaGetSymbolAddress((void**)&vp, g_v);
    cudaGetSymbolAddress((void**)&cp, g_ctx);
    cudaGetSymbolAddress((void**)&ap, g_attn);
    cudaGetSymbolAddress((void**)&ilp, g_invl);

    const size_t out_elems = (size_t)M * D_MODEL;
    const int write_p = ((size_t)out_size > out_elems) ? 1 : 0;
    float* attn = write_p ? (out + out_elems) : ap;

    dim3 gqkv(D_MODEL / 128, M / 128, 3);
    qkv_proj_tc<<<gqkv, 256>>>(Q, Wq, bq, Wk, bk, Wv, bv, qp, kp, vp);

    const int smem_bytes = (int)sizeof(ScoresSmem);
    cudaFuncSetAttribute(scores_exp_tc, cudaFuncAttributeMaxDynamicSharedMemorySize,
                         smem_bytes);
    dim3 gsc(SEQ / 128, B * NHEADS);             // (16, 32)
    scores_exp_tc<<<gsc, 256, smem_bytes>>>(qp, kp, scale, attn, ilp);

    dim3 gpv(SEQ / 128, 1, B * NHEADS);          // (16, 1, 32)
    pv_norm_tc<<<gpv, 256>>>(attn, vp, ilp, cp, write_p);

    dim3 gproj(D_MODEL / 128, M / 128);
    gemm_bias_tc<<<gproj, 256>>>(cp, Wo, bo, out);
}

// round 7
// speedup vs baseline: 2.7932x; 1.0974x over previous
#include <cuda_runtime.h>
#include <cuda_bf16.h>
#include <math.h>
#include <stdint.h>

#define D_MODEL 1024
#define SEQ     2048
#define NHEADS  16
#define HEADDIM 64
#define MAXB    2

// ---------------------------------------------------------------------------
// Device scratch
// ---------------------------------------------------------------------------
__device__ float g_q[MAXB * SEQ * D_MODEL];
__device__ float g_k[MAXB * SEQ * D_MODEL];
__device__ float g_v[MAXB * SEQ * D_MODEL];
__device__ float g_ctx[MAXB * SEQ * D_MODEL];
__device__ float g_invl[MAXB * NHEADS * SEQ];
__device__ float g_attn[(size_t)MAXB * NHEADS * SEQ * SEQ];

// ---------------------------------------------------------------------------
// tf32 helpers
// ---------------------------------------------------------------------------
__device__ __forceinline__ uint32_t f2tf32(float x) {
    uint32_t r;
    asm("cvt.rna.tf32.f32 %0, %1;" : "=r"(r) : "f"(x));
    return r;
}

__device__ __forceinline__ float ex2(float x) {
    float r;
    asm("ex2.approx.f32 %0, %1;" : "=f"(r) : "f"(x));
    return r;
}

__device__ __forceinline__ void mma_tf32(float* c, const uint32_t* a, const uint32_t* b) {
    asm("mma.sync.aligned.m16n8k8.row.col.f32.tf32.tf32.f32 "
        "{%0,%1,%2,%3}, {%4,%5,%6,%7}, {%8,%9}, {%0,%1,%2,%3};"
        : "+f"(c[0]), "+f"(c[1]), "+f"(c[2]), "+f"(c[3])
        : "r"(a[0]), "r"(a[1]), "r"(a[2]), "r"(a[3]), "r"(b[0]), "r"(b[1]));
}

// ---------------------------------------------------------------------------
// Projection GEMM with register-staged double buffering
// ---------------------------------------------------------------------------
struct GemmSmem {
    uint4 AF[8][4][33];
    uint2 BF[16][4][33];
};

__device__ __forceinline__ void gemm_body(
    GemmSmem& s, const float* __restrict__ A, const float* __restrict__ W,
    const float* __restrict__ bias, float* __restrict__ C, int m0, int n0)
{
    const int tid  = threadIdx.x;
    const int warp = tid >> 5;
    const int lane = tid & 31;
    const int g    = lane >> 2;
    const int kq   = lane & 3;
    const int wm   = warp >> 1;
    const int wn   = warp & 1;

    float acc[2][8][4] = {};

    // staging registers
    float4 a_lo[2], a_hi[2], b_lo[2], b_hi[2];

    // prologue: load tile k0=0
    #pragma unroll
    for (int i = 0; i < 2; i++) {
        int idx = tid + i * 256;
        int rp = idx >> 3, c4 = (idx & 7) * 4;
        const float* a0 = &A[(size_t)(m0 + (rp >> 3) * 16 + (rp & 7)) * D_MODEL + c4];
        a_lo[i] = *(const float4*)a0;
        a_hi[i] = *(const float4*)(a0 + 8 * D_MODEL);
        int rp2 = idx >> 5, c42 = (idx & 31) * 4;
        const float* b0 = &W[(size_t)((rp2 >> 2) * 8 + (rp2 & 3)) * D_MODEL + n0 + c42];
        b_lo[i] = *(const float4*)b0;
        b_hi[i] = *(const float4*)(b0 + 4 * D_MODEL);
    }

    for (int k0 = 0; k0 < D_MODEL; k0 += 32) {
        // store staged tile to smem (tf32 convert)
        #pragma unroll
        for (int i = 0; i < 2; i++) {
            int idx = tid + i * 256;
            int rp = idx >> 3, c4 = (idx & 7) * 4;
            int mt = rp >> 3, r8 = rp & 7;
            int kb  = c4 >> 3;
            int off = ((c4 >> 2) & 1) * 2;
            uint32_t* base = (uint32_t*)&s.AF[mt][kb][r8 * 4];
            *(uint2*)&base[0 * 4 + off] = make_uint2(f2tf32(a_lo[i].x), f2tf32(a_hi[i].x));
            *(uint2*)&base[1 * 4 + off] = make_uint2(f2tf32(a_lo[i].y), f2tf32(a_hi[i].y));
            *(uint2*)&base[2 * 4 + off] = make_uint2(f2tf32(a_lo[i].z), f2tf32(a_hi[i].z));
            *(uint2*)&base[3 * 4 + off] = make_uint2(f2tf32(a_lo[i].w), f2tf32(a_hi[i].w));
            int rp2 = idx >> 5, c42 = (idx & 31) * 4;
            int kb2 = rp2 >> 2, rq = rp2 & 3;
            int nt = c42 >> 3, gb = c42 & 7;
            s.BF[nt][kb2][(gb + 0) * 4 + rq] = make_uint2(f2tf32(b_lo[i].x), f2tf32(b_hi[i].x));
            s.BF[nt][kb2][(gb + 1) * 4 + rq] = make_uint2(f2tf32(b_lo[i].y), f2tf32(b_hi[i].y));
            s.BF[nt][kb2][(gb + 2) * 4 + rq] = make_uint2(f2tf32(b_lo[i].z), f2tf32(b_hi[i].z));
            s.BF[nt][kb2][(gb + 3) * 4 + rq] = make_uint2(f2tf32(b_lo[i].w), f2tf32(b_hi[i].w));
        }
        __syncthreads();

        // prefetch next tile into regs (overlaps with MMA below)
        if (k0 + 32 < D_MODEL) {
            int kn = k0 + 32;
            #pragma unroll
            for (int i = 0; i < 2; i++) {
                int idx = tid + i * 256;
                int rp = idx >> 3, c4 = (idx & 7) * 4;
                const float* a0 = &A[(size_t)(m0 + (rp >> 3) * 16 + (rp & 7)) * D_MODEL + kn + c4];
                a_lo[i] = *(const float4*)a0;
                a_hi[i] = *(const float4*)(a0 + 8 * D_MODEL);
                int rp2 = idx >> 5, c42 = (idx & 31) * 4;
                const float* b0 = &W[(size_t)(kn + (rp2 >> 2) * 8 + (rp2 & 3)) * D_MODEL + n0 + c42];
                b_lo[i] = *(const float4*)b0;
                b_hi[i] = *(const float4*)(b0 + 4 * D_MODEL);
            }
        }

        #pragma unroll
        for (int kb = 0; kb < 4; kb++) {
            uint4 a[2];
            a[0] = s.AF[wm * 2 + 0][kb][lane];
            a[1] = s.AF[wm * 2 + 1][kb][lane];
            uint2 b[8];
            #pragma unroll
            for (int jn = 0; jn < 8; jn++) b[jn] = s.BF[wn * 8 + jn][kb][lane];
            #pragma unroll
            for (int im = 0; im < 2; im++)
                #pragma unroll
                for (int jn = 0; jn < 8; jn++)
                    mma_tf32(acc[im][jn], (const uint32_t*)&a[im], (const uint32_t*)&b[jn]);
        }
        __syncthreads();
    }

    #pragma unroll
    for (int im = 0; im < 2; im++) {
        int mb = m0 + wm * 32 + im * 16;
        #pragma unroll
        for (int jn = 0; jn < 8; jn++) {
            int n = n0 + wn * 64 + jn * 8 + 2 * kq;
            float b0 = bias[n], b1 = bias[n + 1];
            float* p0 = &C[(size_t)(mb + g) * D_MODEL + n];
            float* p1 = &C[(size_t)(mb + g + 8) * D_MODEL + n];
            p0[0] = acc[im][jn][0] + b0; p0[1] = acc[im][jn][1] + b1;
            p1[0] = acc[im][jn][2] + b0; p1[1] = acc[im][jn][3] + b1;
        }
    }
}

__global__ void __launch_bounds__(256)
qkv_proj_tc(const float* __restrict__ A,
            const float* __restrict__ Wq, const float* __restrict__ bq,
            const float* __restrict__ Wk, const float* __restrict__ bk,
            const float* __restrict__ Wv, const float* __restrict__ bv,
            float* __restrict__ oq, float* __restrict__ ok, float* __restrict__ ov)
{
    __shared__ GemmSmem s;
    const int z = blockIdx.z;
    const float* W    = (z == 0) ? Wq : (z == 1) ? Wk : Wv;
    const float* bias = (z == 0) ? bq : (z == 1) ? bk : bv;
    float*       C    = (z == 0) ? oq : (z == 1) ? ok : ov;
    gemm_body(s, A, W, bias, C, blockIdx.y * 128, blockIdx.x * 128);
}

__global__ void __launch_bounds__(256)
gemm_bias_tc(const float* __restrict__ A, const float* __restrict__ W,
             const float* __restrict__ bias, float* __restrict__ C)
{
    __shared__ GemmSmem s;
    gemm_body(s, A, W, bias, C, blockIdx.y * 128, blockIdx.x * 128);
}

// ---------------------------------------------------------------------------
// scores+exp fused, register-staged K pipeline.
// CTA owns a 128-row strip x all 2048 keys of one (b,h).
// ---------------------------------------------------------------------------
struct ScoresSmem {
    uint4 QF[8][8][33];
    uint2 KF[16][8][33];
    float red[2][128];
};

__global__ void __launch_bounds__(256)
scores_exp_tc(const float* __restrict__ qb, const float* __restrict__ kb_,
              const float* __restrict__ scale_ptr, float* __restrict__ attn,
              float* __restrict__ invl_out)
{
    extern __shared__ char smem_raw[];
    ScoresSmem& sm = *(ScoresSmem*)smem_raw;

    const int tid  = threadIdx.x;
    const int warp = tid >> 5;
    const int lane = tid & 31;
    const int g    = lane >> 2;
    const int kq   = lane & 3;
    const int wm   = warp >> 1;
    const int wn   = warp & 1;

    const int bh = blockIdx.y;
    const int b  = bh >> 4;
    const int h  = bh & 15;
    const int m0 = blockIdx.x * 128;

    const float sc = scale_ptr[0] * 1.44269504088896f;

    const float* qbase = qb  + (size_t)(b * SEQ + m0) * D_MODEL + h * HEADDIM;
    const float* kbase = kb_ + (size_t)b * SEQ * D_MODEL + h * HEADDIM;
    float* pstrip = attn + ((size_t)bh * SEQ + m0) * SEQ;

    // ---- Q strip 128x64 -> QF (once) ----
    #pragma unroll
    for (int k0 = 0; k0 < 64; k0 += 32) {
        #pragma unroll
        for (int i = 0; i < 2; i++) {
            int idx = tid + i * 256;
            int rp = idx >> 3;
            int c4 = (idx & 7) * 4;
            int mt = rp >> 3;
            int r8 = rp & 7;
            const float* a0 = &qbase[(size_t)(mt * 16 + r8) * D_MODEL + k0 + c4];
            float4 vlo = *(const float4*)a0;
            float4 vhi = *(const float4*)(a0 + 8 * D_MODEL);
            int kb  = (k0 + c4) >> 3;
            int off = ((c4 >> 2) & 1) * 2;
            uint32_t* base = (uint32_t*)&sm.QF[mt][kb][r8 * 4];
            *(uint2*)&base[0 * 4 + off] = make_uint2(f2tf32(vlo.x), f2tf32(vhi.x));
            *(uint2*)&base[1 * 4 + off] = make_uint2(f2tf32(vlo.y), f2tf32(vhi.y));
            *(uint2*)&base[2 * 4 + off] = make_uint2(f2tf32(vlo.z), f2tf32(vhi.z));
            *(uint2*)&base[3 * 4 + off] = make_uint2(f2tf32(vlo.w), f2tf32(vhi.w));
        }
    }

    float l_acc[2][2] = {};

    // K staging registers
    float4 k_lo[4], k_hi[4];
    #pragma unroll
    for (int i = 0; i < 4; i++) {
        int idx = tid + i * 256;
        int n  = idx >> 3;
        int c8 = (idx & 7) * 8;
        const float* p = &kbase[(size_t)n * D_MODEL + c8];
        k_lo[i] = *(const float4*)p;
        k_hi[i] = *(const float4*)(p + 4);
    }

    for (int iter = 0; iter < SEQ / 128; iter++) {
        const int n0 = iter * 128;

        // store staged K tile -> KF
        #pragma unroll
        for (int i = 0; i < 4; i++) {
            int idx = tid + i * 256;
            int n  = idx >> 3;
            int c8 = (idx & 7) * 8;
            int nt  = n >> 3;
            int gg  = n & 7;
            int kbk = c8 >> 3;
            sm.KF[nt][kbk][gg * 4 + 0] = make_uint2(f2tf32(k_lo[i].x), f2tf32(k_hi[i].x));
            sm.KF[nt][kbk][gg * 4 + 1] = make_uint2(f2tf32(k_lo[i].y), f2tf32(k_hi[i].y));
            sm.KF[nt][kbk][gg * 4 + 2] = make_uint2(f2tf32(k_lo[i].z), f2tf32(k_hi[i].z));
            sm.KF[nt][kbk][gg * 4 + 3] = make_uint2(f2tf32(k_lo[i].w), f2tf32(k_hi[i].w));
        }
        __syncthreads();

        // prefetch next K tile
        if (iter + 1 < SEQ / 128) {
            #pragma unroll
            for (int i = 0; i < 4; i++) {
                int idx = tid + i * 256;
                int n  = idx >> 3;
                int c8 = (idx & 7) * 8;
                const float* p = &kbase[(size_t)(n0 + 128 + n) * D_MODEL + c8];
                k_lo[i] = *(const float4*)p;
                k_hi[i] = *(const float4*)(p + 4);
            }
        }

        // ---- S tile 128x128 ----
        float acc[2][8][4] = {};
        #pragma unroll
        for (int kb = 0; kb < 8; kb++) {
            uint4 a[2];
            a[0] = sm.QF[wm * 2 + 0][kb][lane];
            a[1] = sm.QF[wm * 2 + 1][kb][lane];
            uint2 bfr[8];
            #pragma unroll
            for (int jn = 0; jn < 8; jn++) bfr[jn] = sm.KF[wn * 8 + jn][kb][lane];
            #pragma unroll
            for (int im = 0; im < 2; im++)
                #pragma unroll
                for (int jn = 0; jn < 8; jn++)
                    mma_tf32(acc[im][jn], (const uint32_t*)&a[im], (const uint32_t*)&bfr[jn]);
        }

        // ---- exp epilogue ----
        #pragma unroll
        for (int im = 0; im < 2; im++) {
            int mb = wm * 32 + im * 16;
            #pragma unroll
            for (int jn = 0; jn < 8; jn++) {
                int n = n0 + wn * 64 + jn * 8 + 2 * kq;
                float pu0 = ex2(acc[im][jn][0] * sc);
                float pu1 = ex2(acc[im][jn][1] * sc);
                float pu2 = ex2(acc[im][jn][2] * sc);
                float pu3 = ex2(acc[im][jn][3] * sc);
                l_acc[im][0] += pu0 + pu1;
                l_acc[im][1] += pu2 + pu3;
                *(float2*)&pstrip[(size_t)(mb + g) * SEQ + n]     = make_float2(pu0, pu1);
                *(float2*)&pstrip[(size_t)(mb + g + 8) * SEQ + n] = make_float2(pu2, pu3);
            }
        }
        __syncthreads();
    }

    // ---- row-sum reduction -> invl ----
    #pragma unroll
    for (int im = 0; im < 2; im++)
        #pragma unroll
        for (int rh = 0; rh < 2; rh++) {
            l_acc[im][rh] += __shfl_xor_sync(0xffffffff, l_acc[im][rh], 1);
            l_acc[im][rh] += __shfl_xor_sync(0xffffffff, l_acc[im][rh], 2);
        }
    if (kq == 0) {
        #pragma unroll
        for (int im = 0; im < 2; im++)
            #pragma unroll
            for (int rh = 0; rh < 2; rh++)
                sm.red[wn][wm * 32 + im * 16 + rh * 8 + g] = l_acc[im][rh];
    }
    __syncthreads();
    if (tid < 128) {
        float l = sm.red[0][tid] + sm.red[1][tid];
        invl_out[(size_t)bh * SEQ + m0 + tid] = 1.0f / l;
    }
}

// ---------------------------------------------------------------------------
// PV + normalization, register-staged pipeline.
// ---------------------------------------------------------------------------
__global__ void __launch_bounds__(256)
pv_norm_tc(float* attn, const float* __restrict__ vb,
           const float* __restrict__ invl_in, float* __restrict__ ctx, int write_p)
{
    __shared__ uint4 PF[8][4][33];
    __shared__ uint2 VF[8][4][33];
    __shared__ float sinvl[128];

    const int tid  = threadIdx.x;
    const int warp = tid >> 5;
    const int lane = tid & 31;
    const int g    = lane >> 2;
    const int kq   = lane & 3;
    const int wm   = warp >> 1;
    const int wn   = warp & 1;

    const int bh = blockIdx.z;
    const int b  = bh >> 4;
    const int h  = bh & 15;
    const int m0 = blockIdx.x * 128;

    float* pbase = attn + ((size_t)bh * SEQ + m0) * SEQ;
    const float* vbase = vb + (size_t)b * SEQ * D_MODEL + h * HEADDIM;

    if (tid < 128) sinvl[tid] = invl_in[(size_t)bh * SEQ + m0 + tid];
    __syncthreads();

    float acc[2][4][4] = {};

    // staging
    float4 p_lo[2], p_hi[2], v_lo, v_hi;
    #pragma unroll
    for (int i = 0; i < 2; i++) {
        int idx = tid + i * 256;
        int rp = idx >> 3, c4 = (idx & 7) * 4;
        const float* a0 = &pbase[(size_t)((rp >> 3) * 16 + (rp & 7)) * SEQ + c4];
        p_lo[i] = *(const float4*)a0;
        p_hi[i] = *(const float4*)(a0 + 8 * SEQ);
    }
    {
        int rp = tid >> 4, c4 = (tid & 15) * 4;
        const float* v0 = &vbase[(size_t)((rp >> 2) * 8 + (rp & 3)) * D_MODEL + c4];
        v_lo = *(const float4*)v0;
        v_hi = *(const float4*)(v0 + 4 * D_MODEL);
    }

    for (int k0 = 0; k0 < SEQ; k0 += 32) {
        // store staged tiles (+ normalized P rewrite for this tile)
        #pragma unroll
        for (int i = 0; i < 2; i++) {
            int idx = tid + i * 256;
            int rp = idx >> 3, c4 = (idx & 7) * 4;
            int mt = rp >> 3, r8 = rp & 7;
            if (write_p) {
                float il0 = sinvl[mt * 16 + r8];
                float il1 = sinvl[mt * 16 + r8 + 8];
                float* a0 = &pbase[(size_t)(mt * 16 + r8) * SEQ + k0 + c4];
                *(float4*)a0 = make_float4(p_lo[i].x * il0, p_lo[i].y * il0,
                                           p_lo[i].z * il0, p_lo[i].w * il0);
                *(float4*)(a0 + 8 * SEQ) = make_float4(p_hi[i].x * il1, p_hi[i].y * il1,
                                                       p_hi[i].z * il1, p_hi[i].w * il1);
            }
            int kbk = c4 >> 3;
            int off = ((c4 >> 2) & 1) * 2;
            uint32_t* base = (uint32_t*)&PF[mt][kbk][r8 * 4];
            *(uint2*)&base[0 * 4 + off] = make_uint2(f2tf32(p_lo[i].x), f2tf32(p_hi[i].x));
            *(uint2*)&base[1 * 4 + off] = make_uint2(f2tf32(p_lo[i].y), f2tf32(p_hi[i].y));
            *(uint2*)&base[2 * 4 + off] = make_uint2(f2tf32(p_lo[i].z), f2tf32(p_hi[i].z));
            *(uint2*)&base[3 * 4 + off] = make_uint2(f2tf32(p_lo[i].w), f2tf32(p_hi[i].w));
        }
        {
            int rp = tid >> 4, c4 = (tid & 15) * 4;
            int kbk = rp >> 2, rq = rp & 3;
            int nt = c4 >> 3, gb = c4 & 7;
            VF[nt][kbk][(gb + 0) * 4 + rq] = make_uint2(f2tf32(v_lo.x), f2tf32(v_hi.x));
            VF[nt][kbk][(gb + 1) * 4 + rq] = make_uint2(f2tf32(v_lo.y), f2tf32(v_hi.y));
            VF[nt][kbk][(gb + 2) * 4 + rq] = make_uint2(f2tf32(v_lo.z), f2tf32(v_hi.z));
            VF[nt][kbk][(gb + 3) * 4 + rq] = make_uint2(f2tf32(v_lo.w), f2tf32(v_hi.w));
        }
        __syncthreads();

        // prefetch next tiles
        if (k0 + 32 < SEQ) {
            int kn = k0 + 32;
            #pragma unroll
            for (int i = 0; i < 2; i++) {
                int idx = tid + i * 256;
                int rp = idx >> 3, c4 = (idx & 7) * 4;
                const float* a0 = &pbase[(size_t)((rp >> 3) * 16 + (rp & 7)) * SEQ + kn + c4];
                p_lo[i] = *(const float4*)a0;
                p_hi[i] = *(const float4*)(a0 + 8 * SEQ);
            }
            int rp = tid >> 4, c4 = (tid & 15) * 4;
            const float* v0 = &vbase[(size_t)(kn + (rp >> 2) * 8 + (rp & 3)) * D_MODEL + c4];
            v_lo = *(const float4*)v0;
            v_hi = *(const float4*)(v0 + 4 * D_MODEL);
        }

        #pragma unroll
        for (int kbk = 0; kbk < 4; kbk++) {
            uint4 a[2];
            a[0] = PF[wm * 2 + 0][kbk][lane];
            a[1] = PF[wm * 2 + 1][kbk][lane];
            uint2 bfr[4];
            #pragma unroll
            for (int jn = 0; jn < 4; jn++) bfr[jn] = VF[wn * 4 + jn][kbk][lane];
            #pragma unroll
            for (int im = 0; im < 2; im++)
                #pragma unroll
                for (int jn = 0; jn < 4; jn++)
                    mma_tf32(acc[im][jn], (const uint32_t*)&a[im], (const uint32_t*)&bfr[jn]);
        }
        __syncthreads();
    }

    #pragma unroll
    for (int im = 0; im < 2; im++) {
        int mr = wm * 32 + im * 16;
        float il0 = sinvl[mr + g];
        float il1 = sinvl[mr + g + 8];
        int mb = b * SEQ + m0 + mr;
        #pragma unroll
        for (int jn = 0; jn < 4; jn++) {
            int n = h * HEADDIM + wn * 32 + jn * 8 + 2 * kq;
            float* p0 = &ctx[(size_t)(mb + g) * D_MODEL + n];
            float* p1 = &ctx[(size_t)(mb + g + 8) * D_MODEL + n];
            p0[0] = acc[im][jn][0] * il0; p0[1] = acc[im][jn][1] * il0;
            p1[0] = acc[im][jn][2] * il1; p1[1] = acc[im][jn][3] * il1;
        }
    }
}

// ---------------------------------------------------------------------------
// Launch
// ---------------------------------------------------------------------------
extern "C" void kernel_launch(void* const* d_in, const int* in_sizes, int n_in,
                              void* d_out, int out_size)
{
    const float* Q     = (const float*)d_in[0];
    const float* Wq    = (const float*)d_in[1];
    const float* bq    = (const float*)d_in[2];
    const float* Wk    = (const float*)d_in[3];
    const float* bk    = (const float*)d_in[4];
    const float* Wv    = (const float*)d_in[5];
    const float* bv    = (const float*)d_in[6];
    const float* Wo    = (const float*)d_in[7];
    const float* bo    = (const float*)d_in[8];
    const float* scale = (const float*)d_in[9];

    const int M = in_sizes[0] / D_MODEL;
    const int B = M / SEQ;

    float* out = (float*)d_out;

    float *qp, *kp, *vp, *cp, *ap, *ilp;
    cudaGetSymbolAddress((void**)&qp, g_q);
    cudaGetSymbolAddress((void**)&kp, g_k);
    cudaGetSymbolAddress((void**)&vp, g_v);
    cudaGetSymbolAddress((void**)&cp, g_ctx);
    cudaGetSymbolAddress((void**)&ap, g_attn);
    cudaGetSymbolAddress((void**)&ilp, g_invl);

    const size_t out_elems = (size_t)M * D_MODEL;
    const int write_p = ((size_t)out_size > out_elems) ? 1 : 0;
    float* attn = write_p ? (out + out_elems) : ap;

    dim3 gqkv(D_MODEL / 128, M / 128, 3);
    qkv_proj_tc<<<gqkv, 256>>>(Q, Wq, bq, Wk, bk, Wv, bv, qp, kp, vp);

    const int smem_bytes = (int)sizeof(ScoresSmem);
    cudaFuncSetAttribute(scores_exp_tc, cudaFuncAttributeMaxDynamicSharedMemorySize,
                         smem_bytes);
    dim3 gsc(SEQ / 128, B * NHEADS);
    scores_exp_tc<<<gsc, 256, smem_bytes>>>(qp, kp, scale, attn, ilp);

    dim3 gpv(SEQ / 128, 1, B * NHEADS);
    pv_norm_tc<<<gpv, 256>>>(attn, vp, ilp, cp, write_p);

    dim3 gproj(D_MODEL / 128, M / 128);
    gemm_bias_tc<<<gproj, 256>>>(cp, Wo, bo, out);
}

// round 8
// speedup vs baseline: 2.8171x; 1.0086x over previous
#include <cuda_runtime.h>
#include <cuda_bf16.h>
#include <math.h>
#include <stdint.h>

#define D_MODEL 1024
#define SEQ     2048
#define NHEADS  16
#define HEADDIM 64
#define MAXB    2

// ---------------------------------------------------------------------------
// Device scratch
// ---------------------------------------------------------------------------
__device__ float g_q[MAXB * SEQ * D_MODEL];
__device__ float g_k[MAXB * SEQ * D_MODEL];
__device__ float g_v[MAXB * SEQ * D_MODEL];
__device__ float g_ctx[MAXB * SEQ * D_MODEL];
__device__ float g_invl[MAXB * NHEADS * SEQ];
__device__ float g_attn[(size_t)MAXB * NHEADS * SEQ * SEQ];

// ---------------------------------------------------------------------------
// tf32 helpers
// ---------------------------------------------------------------------------
__device__ __forceinline__ uint32_t f2tf32(float x) {
    uint32_t r;
    asm("cvt.rna.tf32.f32 %0, %1;" : "=r"(r) : "f"(x));
    return r;
}

__device__ __forceinline__ float ex2(float x) {
    float r;
    asm("ex2.approx.f32 %0, %1;" : "=f"(r) : "f"(x));
    return r;
}

__device__ __forceinline__ void mma_tf32(float* c, const uint32_t* a, const uint32_t* b) {
    asm("mma.sync.aligned.m16n8k8.row.col.f32.tf32.tf32.f32 "
        "{%0,%1,%2,%3}, {%4,%5,%6,%7}, {%8,%9}, {%0,%1,%2,%3};"
        : "+f"(c[0]), "+f"(c[1]), "+f"(c[2]), "+f"(c[3])
        : "r"(a[0]), "r"(a[1]), "r"(a[2]), "r"(a[3]), "r"(b[0]), "r"(b[1]));
}

// ---------------------------------------------------------------------------
// Projection GEMM: ping-pong SMEM + register staging
// ---------------------------------------------------------------------------
struct GemmSmem {
    uint4 AF[8][4][33];
    uint2 BF[16][4][33];
};

__device__ __forceinline__ void gemm_load_regs(
    const float* __restrict__ A, const float* __restrict__ W,
    int m0, int n0, int k0, int tid,
    float4* a_lo, float4* a_hi, float4* b_lo, float4* b_hi)
{
    #pragma unroll
    for (int i = 0; i < 2; i++) {
        int idx = tid + i * 256;
        int rp = idx >> 3, c4 = (idx & 7) * 4;
        const float* a0 = &A[(size_t)(m0 + (rp >> 3) * 16 + (rp & 7)) * D_MODEL + k0 + c4];
        a_lo[i] = *(const float4*)a0;
        a_hi[i] = *(const float4*)(a0 + 8 * D_MODEL);
        int rp2 = idx >> 5, c42 = (idx & 31) * 4;
        const float* b0 = &W[(size_t)(k0 + (rp2 >> 2) * 8 + (rp2 & 3)) * D_MODEL + n0 + c42];
        b_lo[i] = *(const float4*)b0;
        b_hi[i] = *(const float4*)(b0 + 4 * D_MODEL);
    }
}

__device__ __forceinline__ void gemm_store_smem(
    GemmSmem& s, int tid,
    const float4* a_lo, const float4* a_hi, const float4* b_lo, const float4* b_hi)
{
    #pragma unroll
    for (int i = 0; i < 2; i++) {
        int idx = tid + i * 256;
        int rp = idx >> 3, c4 = (idx & 7) * 4;
        int mt = rp >> 3, r8 = rp & 7;
        int kb  = c4 >> 3;
        int off = ((c4 >> 2) & 1) * 2;
        uint32_t* base = (uint32_t*)&s.AF[mt][kb][r8 * 4];
        *(uint2*)&base[0 * 4 + off] = make_uint2(f2tf32(a_lo[i].x), f2tf32(a_hi[i].x));
        *(uint2*)&base[1 * 4 + off] = make_uint2(f2tf32(a_lo[i].y), f2tf32(a_hi[i].y));
        *(uint2*)&base[2 * 4 + off] = make_uint2(f2tf32(a_lo[i].z), f2tf32(a_hi[i].z));
        *(uint2*)&base[3 * 4 + off] = make_uint2(f2tf32(a_lo[i].w), f2tf32(a_hi[i].w));
        int rp2 = idx >> 5, c42 = (idx & 31) * 4;
        int kb2 = rp2 >> 2, rq = rp2 & 3;
        int nt = c42 >> 3, gb = c42 & 7;
        s.BF[nt][kb2][(gb + 0) * 4 + rq] = make_uint2(f2tf32(b_lo[i].x), f2tf32(b_hi[i].x));
        s.BF[nt][kb2][(gb + 1) * 4 + rq] = make_uint2(f2tf32(b_lo[i].y), f2tf32(b_hi[i].y));
        s.BF[nt][kb2][(gb + 2) * 4 + rq] = make_uint2(f2tf32(b_lo[i].z), f2tf32(b_hi[i].z));
        s.BF[nt][kb2][(gb + 3) * 4 + rq] = make_uint2(f2tf32(b_lo[i].w), f2tf32(b_hi[i].w));
    }
}

__device__ __forceinline__ void gemm_body(
    GemmSmem* bufs, const float* __restrict__ A, const float* __restrict__ W,
    const float* __restrict__ bias, float* __restrict__ C, int m0, int n0)
{
    const int tid  = threadIdx.x;
    const int warp = tid >> 5;
    const int lane = tid & 31;
    const int g    = lane >> 2;
    const int kq   = lane & 3;
    const int wm   = warp >> 1;
    const int wn   = warp & 1;

    float acc[2][8][4] = {};
    float4 a_lo[2], a_hi[2], b_lo[2], b_hi[2];

    gemm_load_regs(A, W, m0, n0, 0, tid, a_lo, a_hi, b_lo, b_hi);
    gemm_store_smem(bufs[0], tid, a_lo, a_hi, b_lo, b_hi);
    __syncthreads();

    const int NT = D_MODEL / 32;
    for (int kt = 0; kt < NT; kt++) {
        GemmSmem& cur = bufs[kt & 1];
        const bool has_next = (kt + 1 < NT);
        if (has_next)
            gemm_load_regs(A, W, m0, n0, (kt + 1) * 32, tid, a_lo, a_hi, b_lo, b_hi);

        #pragma unroll
        for (int kb = 0; kb < 4; kb++) {
            uint4 a[2];
            a[0] = cur.AF[wm * 2 + 0][kb][lane];
            a[1] = cur.AF[wm * 2 + 1][kb][lane];
            uint2 b[8];
            #pragma unroll
            for (int jn = 0; jn < 8; jn++) b[jn] = cur.BF[wn * 8 + jn][kb][lane];
            #pragma unroll
            for (int im = 0; im < 2; im++)
                #pragma unroll
                for (int jn = 0; jn < 8; jn++)
                    mma_tf32(acc[im][jn], (const uint32_t*)&a[im], (const uint32_t*)&b[jn]);
        }

        if (has_next)
            gemm_store_smem(bufs[(kt + 1) & 1], tid, a_lo, a_hi, b_lo, b_hi);
        __syncthreads();
    }

    #pragma unroll
    for (int im = 0; im < 2; im++) {
        int mb = m0 + wm * 32 + im * 16;
        #pragma unroll
        for (int jn = 0; jn < 8; jn++) {
            int n = n0 + wn * 64 + jn * 8 + 2 * kq;
            float b0 = bias[n], b1 = bias[n + 1];
            float* p0 = &C[(size_t)(mb + g) * D_MODEL + n];
            float* p1 = &C[(size_t)(mb + g + 8) * D_MODEL + n];
            p0[0] = acc[im][jn][0] + b0; p0[1] = acc[im][jn][1] + b1;
            p1[0] = acc[im][jn][2] + b0; p1[1] = acc[im][jn][3] + b1;
        }
    }
}

__global__ void __launch_bounds__(256)
qkv_proj_tc(const float* __restrict__ A,
            const float* __restrict__ Wq, const float* __restrict__ bq,
            const float* __restrict__ Wk, const float* __restrict__ bk,
            const float* __restrict__ Wv, const float* __restrict__ bv,
            float* __restrict__ oq, float* __restrict__ ok, float* __restrict__ ov)
{
    extern __shared__ char smem_raw[];
    GemmSmem* bufs = (GemmSmem*)smem_raw;
    const int z = blockIdx.z;
    const float* W    = (z == 0) ? Wq : (z == 1) ? Wk : Wv;
    const float* bias = (z == 0) ? bq : (z == 1) ? bk : bv;
    float*       C    = (z == 0) ? oq : (z == 1) ? ok : ov;
    gemm_body(bufs, A, W, bias, C, blockIdx.y * 128, blockIdx.x * 128);
}

__global__ void __launch_bounds__(256)
gemm_bias_tc(const float* __restrict__ A, const float* __restrict__ W,
             const float* __restrict__ bias, float* __restrict__ C)
{
    extern __shared__ char smem_raw[];
    GemmSmem* bufs = (GemmSmem*)smem_raw;
    gemm_body(bufs, A, W, bias, C, blockIdx.y * 128, blockIdx.x * 128);
}

// ---------------------------------------------------------------------------
// scores+exp fused: ping-pong K buffer; CTA owns 128-row strip x 2048 keys.
// ---------------------------------------------------------------------------
struct ScoresSmem {
    uint4 QF[8][8][33];
    uint2 KF[2][16][8][33];
    float red[2][128];
};

__device__ __forceinline__ void scores_load_k(
    const float* __restrict__ kbase, int n0, int tid, float4* k_lo, float4* k_hi)
{
    #pragma unroll
    for (int i = 0; i < 4; i++) {
        int idx = tid + i * 256;
        int n  = idx >> 3;
        int c8 = (idx & 7) * 8;
        const float* p = &kbase[(size_t)(n0 + n) * D_MODEL + c8];
        k_lo[i] = *(const float4*)p;
        k_hi[i] = *(const float4*)(p + 4);
    }
}

__device__ __forceinline__ void scores_store_k(
    uint2 (*KF)[8][33], int tid, const float4* k_lo, const float4* k_hi)
{
    #pragma unroll
    for (int i = 0; i < 4; i++) {
        int idx = tid + i * 256;
        int n  = idx >> 3;
        int c8 = (idx & 7) * 8;
        int nt  = n >> 3;
        int gg  = n & 7;
        int kbk = c8 >> 3;
        KF[nt][kbk][gg * 4 + 0] = make_uint2(f2tf32(k_lo[i].x), f2tf32(k_hi[i].x));
        KF[nt][kbk][gg * 4 + 1] = make_uint2(f2tf32(k_lo[i].y), f2tf32(k_hi[i].y));
        KF[nt][kbk][gg * 4 + 2] = make_uint2(f2tf32(k_lo[i].z), f2tf32(k_hi[i].z));
        KF[nt][kbk][gg * 4 + 3] = make_uint2(f2tf32(k_lo[i].w), f2tf32(k_hi[i].w));
    }
}

__global__ void __launch_bounds__(256)
scores_exp_tc(const float* __restrict__ qb, const float* __restrict__ kb_,
              const float* __restrict__ scale_ptr, float* __restrict__ attn,
              float* __restrict__ invl_out)
{
    extern __shared__ char smem_raw[];
    ScoresSmem& sm = *(ScoresSmem*)smem_raw;

    const int tid  = threadIdx.x;
    const int warp = tid >> 5;
    const int lane = tid & 31;
    const int g    = lane >> 2;
    const int kq   = lane & 3;
    const int wm   = warp >> 1;
    const int wn   = warp & 1;

    const int bh = blockIdx.y;
    const int b  = bh >> 4;
    const int h  = bh & 15;
    const int m0 = blockIdx.x * 128;

    const float sc = scale_ptr[0] * 1.44269504088896f;

    const float* qbase = qb  + (size_t)(b * SEQ + m0) * D_MODEL + h * HEADDIM;
    const float* kbase = kb_ + (size_t)b * SEQ * D_MODEL + h * HEADDIM;
    float* pstrip = attn + ((size_t)bh * SEQ + m0) * SEQ;

    // ---- Q strip 128x64 -> QF (once) ----
    #pragma unroll
    for (int k0 = 0; k0 < 64; k0 += 32) {
        #pragma unroll
        for (int i = 0; i < 2; i++) {
            int idx = tid + i * 256;
            int rp = idx >> 3;
            int c4 = (idx & 7) * 4;
            int mt = rp >> 3;
            int r8 = rp & 7;
            const float* a0 = &qbase[(size_t)(mt * 16 + r8) * D_MODEL + k0 + c4];
            float4 vlo = *(const float4*)a0;
            float4 vhi = *(const float4*)(a0 + 8 * D_MODEL);
            int kb  = (k0 + c4) >> 3;
            int off = ((c4 >> 2) & 1) * 2;
            uint32_t* base = (uint32_t*)&sm.QF[mt][kb][r8 * 4];
            *(uint2*)&base[0 * 4 + off] = make_uint2(f2tf32(vlo.x), f2tf32(vhi.x));
            *(uint2*)&base[1 * 4 + off] = make_uint2(f2tf32(vlo.y), f2tf32(vhi.y));
            *(uint2*)&base[2 * 4 + off] = make_uint2(f2tf32(vlo.z), f2tf32(vhi.z));
            *(uint2*)&base[3 * 4 + off] = make_uint2(f2tf32(vlo.w), f2tf32(vhi.w));
        }
    }

    float l_acc[2][2] = {};
    float4 k_lo[4], k_hi[4];

    scores_load_k(kbase, 0, tid, k_lo, k_hi);
    scores_store_k(sm.KF[0], tid, k_lo, k_hi);
    __syncthreads();

    const int NIT = SEQ / 128;
    for (int iter = 0; iter < NIT; iter++) {
        const int n0 = iter * 128;
        const bool has_next = (iter + 1 < NIT);
        if (has_next) scores_load_k(kbase, n0 + 128, tid, k_lo, k_hi);

        // ---- S tile 128x128 on current buffer ----
        uint2 (*KFc)[8][33] = sm.KF[iter & 1];
        float acc[2][8][4] = {};
        #pragma unroll
        for (int kb = 0; kb < 8; kb++) {
            uint4 a[2];
            a[0] = sm.QF[wm * 2 + 0][kb][lane];
            a[1] = sm.QF[wm * 2 + 1][kb][lane];
            uint2 bfr[8];
            #pragma unroll
            for (int jn = 0; jn < 8; jn++) bfr[jn] = KFc[wn * 8 + jn][kb][lane];
            #pragma unroll
            for (int im = 0; im < 2; im++)
                #pragma unroll
                for (int jn = 0; jn < 8; jn++)
                    mma_tf32(acc[im][jn], (const uint32_t*)&a[im], (const uint32_t*)&bfr[jn]);
        }

        // ---- exp epilogue ----
        #pragma unroll
        for (int im = 0; im < 2; im++) {
            int mb = wm * 32 + im * 16;
            #pragma unroll
            for (int jn = 0; jn < 8; jn++) {
                int n = n0 + wn * 64 + jn * 8 + 2 * kq;
                float pu0 = ex2(acc[im][jn][0] * sc);
                float pu1 = ex2(acc[im][jn][1] * sc);
                float pu2 = ex2(acc[im][jn][2] * sc);
                float pu3 = ex2(acc[im][jn][3] * sc);
                l_acc[im][0] += pu0 + pu1;
                l_acc[im][1] += pu2 + pu3;
                *(float2*)&pstrip[(size_t)(mb + g) * SEQ + n]     = make_float2(pu0, pu1);
                *(float2*)&pstrip[(size_t)(mb + g + 8) * SEQ + n] = make_float2(pu2, pu3);
            }
        }

        if (has_next) scores_store_k(sm.KF[(iter + 1) & 1], tid, k_lo, k_hi);
        __syncthreads();
    }

    // ---- row-sum reduction -> invl ----
    #pragma unroll
    for (int im = 0; im < 2; im++)
        #pragma unroll
        for (int rh = 0; rh < 2; rh++) {
            l_acc[im][rh] += __shfl_xor_sync(0xffffffff, l_acc[im][rh], 1);
            l_acc[im][rh] += __shfl_xor_sync(0xffffffff, l_acc[im][rh], 2);
        }
    if (kq == 0) {
        #pragma unroll
        for (int im = 0; im < 2; im++)
            #pragma unroll
            for (int rh = 0; rh < 2; rh++)
                sm.red[wn][wm * 32 + im * 16 + rh * 8 + g] = l_acc[im][rh];
    }
    __syncthreads();
    if (tid < 128) {
        float l = sm.red[0][tid] + sm.red[1][tid];
        invl_out[(size_t)bh * SEQ + m0 + tid] = 1.0f / l;
    }
}

// ---------------------------------------------------------------------------
// PV + normalization: ping-pong buffers.
// ---------------------------------------------------------------------------
struct PvSmem {
    uint4 PF[2][8][4][33];
    uint2 VF[2][8][4][33];
    float sinvl[128];
};

__device__ __forceinline__ void pv_load_regs(
    const float* __restrict__ pbase, const float* __restrict__ vbase,
    int k0, int tid, float4* p_lo, float4* p_hi, float4& v_lo, float4& v_hi)
{
    #pragma unroll
    for (int i = 0; i < 2; i++) {
        int idx = tid + i * 256;
        int rp = idx >> 3, c4 = (idx & 7) * 4;
        const float* a0 = &pbase[(size_t)((rp >> 3) * 16 + (rp & 7)) * SEQ + k0 + c4];
        p_lo[i] = *(const float4*)a0;
        p_hi[i] = *(const float4*)(a0 + 8 * SEQ);
    }
    int rp = tid >> 4, c4 = (tid & 15) * 4;
    const float* v0 = &vbase[(size_t)(k0 + (rp >> 2) * 8 + (rp & 3)) * D_MODEL + c4];
    v_lo = *(const float4*)v0;
    v_hi = *(const float4*)(v0 + 4 * D_MODEL);
}

__device__ __forceinline__ void pv_store_smem(
    uint4 (*PF)[4][33], uint2 (*VF)[4][33], float* pbase, const float* sinvl,
    int k0, int tid, int write_p,
    const float4* p_lo, const float4* p_hi, const float4& v_lo, const float4& v_hi)
{
    #pragma unroll
    for (int i = 0; i < 2; i++) {
        int idx = tid + i * 256;
        int rp = idx >> 3, c4 = (idx & 7) * 4;
        int mt = rp >> 3, r8 = rp & 7;
        if (write_p) {
            float il0 = sinvl[mt * 16 + r8];
            float il1 = sinvl[mt * 16 + r8 + 8];
            float* a0 = &pbase[(size_t)(mt * 16 + r8) * SEQ + k0 + c4];
            *(float4*)a0 = make_float4(p_lo[i].x * il0, p_lo[i].y * il0,
                                       p_lo[i].z * il0, p_lo[i].w * il0);
            *(float4*)(a0 + 8 * SEQ) = make_float4(p_hi[i].x * il1, p_hi[i].y * il1,
                                                   p_hi[i].z * il1, p_hi[i].w * il1);
        }
        int kbk = c4 >> 3;
        int off = ((c4 >> 2) & 1) * 2;
        uint32_t* base = (uint32_t*)&PF[mt][kbk][r8 * 4];
        *(uint2*)&base[0 * 4 + off] = make_uint2(f2tf32(p_lo[i].x), f2tf32(p_hi[i].x));
        *(uint2*)&base[1 * 4 + off] = make_uint2(f2tf32(p_lo[i].y), f2tf32(p_hi[i].y));
        *(uint2*)&base[2 * 4 + off] = make_uint2(f2tf32(p_lo[i].z), f2tf32(p_hi[i].z));
        *(uint2*)&base[3 * 4 + off] = make_uint2(f2tf32(p_lo[i].w), f2tf32(p_hi[i].w));
    }
    {
        int rp = tid >> 4, c4 = (tid & 15) * 4;
        int kbk = rp >> 2, rq = rp & 3;
        int nt = c4 >> 3, gb = c4 & 7;
        VF[nt][kbk][(gb + 0) * 4 + rq] = make_uint2(f2tf32(v_lo.x), f2tf32(v_hi.x));
        VF[nt][kbk][(gb + 1) * 4 + rq] = make_uint2(f2tf32(v_lo.y), f2tf32(v_hi.y));
        VF[nt][kbk][(gb + 2) * 4 + rq] = make_uint2(f2tf32(v_lo.z), f2tf32(v_hi.z));
        VF[nt][kbk][(gb + 3) * 4 + rq] = make_uint2(f2tf32(v_lo.w), f2tf32(v_hi.w));
    }
}

__global__ void __launch_bounds__(256)
pv_norm_tc(float* attn, const float* __restrict__ vb,
           const float* __restrict__ invl_in, float* __restrict__ ctx, int write_p)
{
    extern __shared__ char smem_raw[];
    PvSmem& sm = *(PvSmem*)smem_raw;

    const int tid  = threadIdx.x;
    const int warp = tid >> 5;
    const int lane = tid & 31;
    const int g    = lane >> 2;
    const int kq   = lane & 3;
    const int wm   = warp >> 1;
    const int wn   = warp & 1;

    const int bh = blockIdx.z;
    const int b  = bh >> 4;
    const int h  = bh & 15;
    const int m0 = blockIdx.x * 128;

    float* pbase = attn + ((size_t)bh * SEQ + m0) * SEQ;
    const float* vbase = vb + (size_t)b * SEQ * D_MODEL + h * HEADDIM;

    if (tid < 128) sm.sinvl[tid] = invl_in[(size_t)bh * SEQ + m0 + tid];
    __syncthreads();

    float acc[2][4][4] = {};
    float4 p_lo[2], p_hi[2], v_lo, v_hi;

    pv_load_regs(pbase, vbase, 0, tid, p_lo, p_hi, v_lo, v_hi);
    pv_store_smem(sm.PF[0], sm.VF[0], pbase, sm.sinvl, 0, tid, write_p,
                  p_lo, p_hi, v_lo, v_hi);
    __syncthreads();

    const int NT = SEQ / 32;
    for (int kt = 0; kt < NT; kt++) {
        const bool has_next = (kt + 1 < NT);
        if (has_next)
            pv_load_regs(pbase, vbase, (kt + 1) * 32, tid, p_lo, p_hi, v_lo, v_hi);

        uint4 (*PFc)[4][33] = sm.PF[kt & 1];
        uint2 (*VFc)[4][33] = sm.VF[kt & 1];
        #pragma unroll
        for (int kbk = 0; kbk < 4; kbk++) {
            uint4 a[2];
            a[0] = PFc[wm * 2 + 0][kbk][lane];
            a[1] = PFc[wm * 2 + 1][kbk][lane];
            uint2 bfr[4];
            #pragma unroll
            for (int jn = 0; jn < 4; jn++) bfr[jn] = VFc[wn * 4 + jn][kbk][lane];
            #pragma unroll
            for (int im = 0; im < 2; im++)
                #pragma unroll
                for (int jn = 0; jn < 4; jn++)
                    mma_tf32(acc[im][jn], (const uint32_t*)&a[im], (const uint32_t*)&bfr[jn]);
        }

        if (has_next)
            pv_store_smem(sm.PF[(kt + 1) & 1], sm.VF[(kt + 1) & 1], pbase, sm.sinvl,
                          (kt + 1) * 32, tid, write_p, p_lo, p_hi, v_lo, v_hi);
        __syncthreads();
    }

    #pragma unroll
    for (int im = 0; im < 2; im++) {
        int mr = wm * 32 + im * 16;
        float il0 = sm.sinvl[mr + g];
        float il1 = sm.sinvl[mr + g + 8];
        int mb = b * SEQ + m0 + mr;
        #pragma unroll
        for (int jn = 0; jn < 4; jn++) {
            int n = h * HEADDIM + wn * 32 + jn * 8 + 2 * kq;
            float* p0 = &ctx[(size_t)(mb + g) * D_MODEL + n];
            float* p1 = &ctx[(size_t)(mb + g + 8) * D_MODEL + n];
            p0[0] = acc[im][jn][0] * il0; p0[1] = acc[im][jn][1] * il0;
            p1[0] = acc[im][jn][2] * il1; p1[1] = acc[im][jn][3] * il1;
        }
    }
}

// ---------------------------------------------------------------------------
// Launch
// ---------------------------------------------------------------------------
extern "C" void kernel_launch(void* const* d_in, const int* in_sizes, int n_in,
                              void* d_out, int out_size)
{
    const float* Q     = (const float*)d_in[0];
    const float* Wq    = (const float*)d_in[1];
    const float* bq    = (const float*)d_in[2];
    const float* Wk    = (const float*)d_in[3];
    const float* bk    = (const float*)d_in[4];
    const float* Wv    = (const float*)d_in[5];
    const float* bv    = (const float*)d_in[6];
    const float* Wo    = (const float*)d_in[7];
    const float* bo    = (const float*)d_in[8];
    const float* scale = (const float*)d_in[9];

    const int M = in_sizes[0] / D_MODEL;
    const int B = M / SEQ;

    float* out = (float*)d_out;

    float *qp, *kp, *vp, *cp, *ap, *ilp;
    cudaGetSymbolAddress((void**)&qp, g_q);
    cudaGetSymbolAddress((void**)&kp, g_k);
    cudaGetSymbolAddress((void**)&vp, g_v);
    cudaGetSymbolAddress((void**)&cp, g_ctx);
    cudaGetSymbolAddress((void**)&ap, g_attn);
    cudaGetSymbolAddress((void**)&ilp, g_invl);

    const size_t out_elems = (size_t)M * D_MODEL;
    const int write_p = ((size_t)out_size > out_elems) ? 1 : 0;
    float* attn = write_p ? (out + out_elems) : ap;

    const int gemm_smem   = (int)(2 * sizeof(GemmSmem));
    const int scores_smem = (int)sizeof(ScoresSmem);
    const int pv_smem     = (int)sizeof(PvSmem);
    static int attr_done = 0;
    if (!attr_done) {
        cudaFuncSetAttribute(qkv_proj_tc, cudaFuncAttributeMaxDynamicSharedMemorySize, gemm_smem);
        cudaFuncSetAttribute(gemm_bias_tc, cudaFuncAttributeMaxDynamicSharedMemorySize, gemm_smem);
        cudaFuncSetAttribute(scores_exp_tc, cudaFuncAttributeMaxDynamicSharedMemorySize, scores_smem);
        cudaFuncSetAttribute(pv_norm_tc, cudaFuncAttributeMaxDynamicSharedMemorySize, pv_smem);
        attr_done = 1;
    }

    dim3 gqkv(D_MODEL / 128, M / 128, 3);
    qkv_proj_tc<<<gqkv, 256, gemm_smem>>>(Q, Wq, bq, Wk, bk, Wv, bv, qp, kp, vp);

    dim3 gsc(SEQ / 128, B * NHEADS);
    scores_exp_tc<<<gsc, 256, scores_smem>>>(qp, kp, scale, attn, ilp);

    dim3 gpv(SEQ / 128, 1, B * NHEADS);
    pv_norm_tc<<<gpv, 256, pv_smem>>>(attn, vp, ilp, cp, write_p);

    dim3 gproj(D_MODEL / 128, M / 128);
    gemm_bias_tc<<<gproj, 256, gemm_smem>>>(cp, Wo, bo, out);
}

// round 9
// speedup vs baseline: 2.9747x; 1.0560x over previous
#include <cuda_runtime.h>
#include <cuda_bf16.h>
#include <math.h>
#include <stdint.h>

#define D_MODEL 1024
#define SEQ     2048
#define NHEADS  16
#define HEADDIM 64
#define MAXB    2

// ---------------------------------------------------------------------------
// Device scratch
// ---------------------------------------------------------------------------
__device__ float g_q[MAXB * SEQ * D_MODEL];
__device__ float g_k[MAXB * SEQ * D_MODEL];
__device__ float g_v[MAXB * SEQ * D_MODEL];
__device__ float g_ctx[MAXB * SEQ * D_MODEL];
__device__ float g_invl[MAXB * NHEADS * SEQ];
__device__ float g_attn[(size_t)MAXB * NHEADS * SEQ * SEQ];

// ---------------------------------------------------------------------------
// tf32 helpers
// ---------------------------------------------------------------------------
__device__ __forceinline__ uint32_t f2tf32(float x) {
    uint32_t r;
    asm("cvt.rna.tf32.f32 %0, %1;" : "=r"(r) : "f"(x));
    return r;
}

__device__ __forceinline__ float ex2(float x) {
    float r;
    asm("ex2.approx.f32 %0, %1;" : "=f"(r) : "f"(x));
    return r;
}

__device__ __forceinline__ void mma_tf32(float* c, const uint32_t* a, const uint32_t* b) {
    asm("mma.sync.aligned.m16n8k8.row.col.f32.tf32.tf32.f32 "
        "{%0,%1,%2,%3}, {%4,%5,%6,%7}, {%8,%9}, {%0,%1,%2,%3};"
        : "+f"(c[0]), "+f"(c[1]), "+f"(c[2]), "+f"(c[3])
        : "r"(a[0]), "r"(a[1]), "r"(a[2]), "r"(a[3]), "r"(b[0]), "r"(b[1]));
}

// ---------------------------------------------------------------------------
// Projection GEMM: ping-pong SMEM + register staging, 2 CTAs/SM
// ---------------------------------------------------------------------------
struct GemmSmem {
    uint4 AF[8][4][33];
    uint2 BF[16][4][33];
};

__device__ __forceinline__ void gemm_load_regs(
    const float* __restrict__ A, const float* __restrict__ W,
    int m0, int n0, int k0, int tid,
    float4* a_lo, float4* a_hi, float4* b_lo, float4* b_hi)
{
    #pragma unroll
    for (int i = 0; i < 2; i++) {
        int idx = tid + i * 256;
        int rp = idx >> 3, c4 = (idx & 7) * 4;
        const float* a0 = &A[(size_t)(m0 + (rp >> 3) * 16 + (rp & 7)) * D_MODEL + k0 + c4];
        a_lo[i] = *(const float4*)a0;
        a_hi[i] = *(const float4*)(a0 + 8 * D_MODEL);
        int rp2 = idx >> 5, c42 = (idx & 31) * 4;
        const float* b0 = &W[(size_t)(k0 + (rp2 >> 2) * 8 + (rp2 & 3)) * D_MODEL + n0 + c42];
        b_lo[i] = *(const float4*)b0;
        b_hi[i] = *(const float4*)(b0 + 4 * D_MODEL);
    }
}

__device__ __forceinline__ void gemm_store_smem(
    GemmSmem& s, int tid,
    const float4* a_lo, const float4* a_hi, const float4* b_lo, const float4* b_hi)
{
    #pragma unroll
    for (int i = 0; i < 2; i++) {
        int idx = tid + i * 256;
        int rp = idx >> 3, c4 = (idx & 7) * 4;
        int mt = rp >> 3, r8 = rp & 7;
        int kb  = c4 >> 3;
        int off = ((c4 >> 2) & 1) * 2;
        uint32_t* base = (uint32_t*)&s.AF[mt][kb][r8 * 4];
        *(uint2*)&base[0 * 4 + off] = make_uint2(f2tf32(a_lo[i].x), f2tf32(a_hi[i].x));
        *(uint2*)&base[1 * 4 + off] = make_uint2(f2tf32(a_lo[i].y), f2tf32(a_hi[i].y));
        *(uint2*)&base[2 * 4 + off] = make_uint2(f2tf32(a_lo[i].z), f2tf32(a_hi[i].z));
        *(uint2*)&base[3 * 4 + off] = make_uint2(f2tf32(a_lo[i].w), f2tf32(a_hi[i].w));
        int rp2 = idx >> 5, c42 = (idx & 31) * 4;
        int kb2 = rp2 >> 2, rq = rp2 & 3;
        int nt = c42 >> 3, gb = c42 & 7;
        s.BF[nt][kb2][(gb + 0) * 4 + rq] = make_uint2(f2tf32(b_lo[i].x), f2tf32(b_hi[i].x));
        s.BF[nt][kb2][(gb + 1) * 4 + rq] = make_uint2(f2tf32(b_lo[i].y), f2tf32(b_hi[i].y));
        s.BF[nt][kb2][(gb + 2) * 4 + rq] = make_uint2(f2tf32(b_lo[i].z), f2tf32(b_hi[i].z));
        s.BF[nt][kb2][(gb + 3) * 4 + rq] = make_uint2(f2tf32(b_lo[i].w), f2tf32(b_hi[i].w));
    }
}

__device__ __forceinline__ void gemm_body(
    GemmSmem* bufs, const float* __restrict__ A, const float* __restrict__ W,
    const float* __restrict__ bias, float* __restrict__ C, int m0, int n0)
{
    const int tid  = threadIdx.x;
    const int warp = tid >> 5;
    const int lane = tid & 31;
    const int g    = lane >> 2;
    const int kq   = lane & 3;
    const int wm   = warp >> 1;
    const int wn   = warp & 1;

    float acc[2][8][4] = {};
    float4 a_lo[2], a_hi[2], b_lo[2], b_hi[2];

    gemm_load_regs(A, W, m0, n0, 0, tid, a_lo, a_hi, b_lo, b_hi);
    gemm_store_smem(bufs[0], tid, a_lo, a_hi, b_lo, b_hi);
    __syncthreads();

    const int NT = D_MODEL / 32;
    for (int kt = 0; kt < NT; kt++) {
        GemmSmem& cur = bufs[kt & 1];
        const bool has_next = (kt + 1 < NT);
        if (has_next)
            gemm_load_regs(A, W, m0, n0, (kt + 1) * 32, tid, a_lo, a_hi, b_lo, b_hi);

        #pragma unroll
        for (int kb = 0; kb < 4; kb++) {
            uint4 a[2];
            a[0] = cur.AF[wm * 2 + 0][kb][lane];
            a[1] = cur.AF[wm * 2 + 1][kb][lane];
            uint2 b[8];
            #pragma unroll
            for (int jn = 0; jn < 8; jn++) b[jn] = cur.BF[wn * 8 + jn][kb][lane];
            #pragma unroll
            for (int im = 0; im < 2; im++)
                #pragma unroll
                for (int jn = 0; jn < 8; jn++)
                    mma_tf32(acc[im][jn], (const uint32_t*)&a[im], (const uint32_t*)&b[jn]);
        }

        if (has_next)
            gemm_store_smem(bufs[(kt + 1) & 1], tid, a_lo, a_hi, b_lo, b_hi);
        __syncthreads();
    }

    #pragma unroll
    for (int im = 0; im < 2; im++) {
        int mb = m0 + wm * 32 + im * 16;
        #pragma unroll
        for (int jn = 0; jn < 8; jn++) {
            int n = n0 + wn * 64 + jn * 8 + 2 * kq;
            float b0 = bias[n], b1 = bias[n + 1];
            float* p0 = &C[(size_t)(mb + g) * D_MODEL + n];
            float* p1 = &C[(size_t)(mb + g + 8) * D_MODEL + n];
            p0[0] = acc[im][jn][0] + b0; p0[1] = acc[im][jn][1] + b1;
            p1[0] = acc[im][jn][2] + b0; p1[1] = acc[im][jn][3] + b1;
        }
    }
}

__global__ void __launch_bounds__(256, 2)
qkv_proj_tc(const float* __restrict__ A,
            const float* __restrict__ Wq, const float* __restrict__ bq,
            const float* __restrict__ Wk, const float* __restrict__ bk,
            const float* __restrict__ Wv, const float* __restrict__ bv,
            float* __restrict__ oq, float* __restrict__ ok, float* __restrict__ ov)
{
    extern __shared__ char smem_raw[];
    GemmSmem* bufs = (GemmSmem*)smem_raw;
    const int z = blockIdx.z;
    const float* W    = (z == 0) ? Wq : (z == 1) ? Wk : Wv;
    const float* bias = (z == 0) ? bq : (z == 1) ? bk : bv;
    float*       C    = (z == 0) ? oq : (z == 1) ? ok : ov;
    gemm_body(bufs, A, W, bias, C, blockIdx.y * 128, blockIdx.x * 128);
}

__global__ void __launch_bounds__(256, 2)
gemm_bias_tc(const float* __restrict__ A, const float* __restrict__ W,
             const float* __restrict__ bias, float* __restrict__ C)
{
    extern __shared__ char smem_raw[];
    GemmSmem* bufs = (GemmSmem*)smem_raw;
    gemm_body(bufs, A, W, bias, C, blockIdx.y * 128, blockIdx.x * 128);
}

// ---------------------------------------------------------------------------
// scores+exp fused: ping-pong K buffer; CTA owns 128-row strip x 2048 keys.
// ---------------------------------------------------------------------------
struct ScoresSmem {
    uint4 QF[8][8][33];
    uint2 KF[2][16][8][33];
    float red[2][128];
};

__device__ __forceinline__ void scores_load_k(
    const float* __restrict__ kbase, int n0, int tid, float4* k_lo, float4* k_hi)
{
    #pragma unroll
    for (int i = 0; i < 4; i++) {
        int idx = tid + i * 256;
        int n  = idx >> 3;
        int c8 = (idx & 7) * 8;
        const float* p = &kbase[(size_t)(n0 + n) * D_MODEL + c8];
        k_lo[i] = *(const float4*)p;
        k_hi[i] = *(const float4*)(p + 4);
    }
}

__device__ __forceinline__ void scores_store_k(
    uint2 (*KF)[8][33], int tid, const float4* k_lo, const float4* k_hi)
{
    #pragma unroll
    for (int i = 0; i < 4; i++) {
        int idx = tid + i * 256;
        int n  = idx >> 3;
        int c8 = (idx & 7) * 8;
        int nt  = n >> 3;
        int gg  = n & 7;
        int kbk = c8 >> 3;
        KF[nt][kbk][gg * 4 + 0] = make_uint2(f2tf32(k_lo[i].x), f2tf32(k_hi[i].x));
        KF[nt][kbk][gg * 4 + 1] = make_uint2(f2tf32(k_lo[i].y), f2tf32(k_hi[i].y));
        KF[nt][kbk][gg * 4 + 2] = make_uint2(f2tf32(k_lo[i].z), f2tf32(k_hi[i].z));
        KF[nt][kbk][gg * 4 + 3] = make_uint2(f2tf32(k_lo[i].w), f2tf32(k_hi[i].w));
    }
}

__global__ void __launch_bounds__(256, 2)
scores_exp_tc(const float* __restrict__ qb, const float* __restrict__ kb_,
              const float* __restrict__ scale_ptr, float* __restrict__ attn,
              float* __restrict__ invl_out)
{
    extern __shared__ char smem_raw[];
    ScoresSmem& sm = *(ScoresSmem*)smem_raw;

    const int tid  = threadIdx.x;
    const int warp = tid >> 5;
    const int lane = tid & 31;
    const int g    = lane >> 2;
    const int kq   = lane & 3;
    const int wm   = warp >> 1;
    const int wn   = warp & 1;

    const int bh = blockIdx.y;
    const int b  = bh >> 4;
    const int h  = bh & 15;
    const int m0 = blockIdx.x * 128;

    const float sc = scale_ptr[0] * 1.44269504088896f;

    const float* qbase = qb  + (size_t)(b * SEQ + m0) * D_MODEL + h * HEADDIM;
    const float* kbase = kb_ + (size_t)b * SEQ * D_MODEL + h * HEADDIM;
    float* pstrip = attn + ((size_t)bh * SEQ + m0) * SEQ;

    // ---- Q strip 128x64 -> QF (once) ----
    #pragma unroll
    for (int k0 = 0; k0 < 64; k0 += 32) {
        #pragma unroll
        for (int i = 0; i < 2; i++) {
            int idx = tid + i * 256;
            int rp = idx >> 3;
            int c4 = (idx & 7) * 4;
            int mt = rp >> 3;
            int r8 = rp & 7;
            const float* a0 = &qbase[(size_t)(mt * 16 + r8) * D_MODEL + k0 + c4];
            float4 vlo = *(const float4*)a0;
            float4 vhi = *(const float4*)(a0 + 8 * D_MODEL);
            int kb  = (k0 + c4) >> 3;
            int off = ((c4 >> 2) & 1) * 2;
            uint32_t* base = (uint32_t*)&sm.QF[mt][kb][r8 * 4];
            *(uint2*)&base[0 * 4 + off] = make_uint2(f2tf32(vlo.x), f2tf32(vhi.x));
            *(uint2*)&base[1 * 4 + off] = make_uint2(f2tf32(vlo.y), f2tf32(vhi.y));
            *(uint2*)&base[2 * 4 + off] = make_uint2(f2tf32(vlo.z), f2tf32(vhi.z));
            *(uint2*)&base[3 * 4 + off] = make_uint2(f2tf32(vlo.w), f2tf32(vhi.w));
        }
    }

    float l_acc[2][2] = {};
    float4 k_lo[4], k_hi[4];

    scores_load_k(kbase, 0, tid, k_lo, k_hi);
    scores_store_k(sm.KF[0], tid, k_lo, k_hi);
    __syncthreads();

    const int NIT = SEQ / 128;
    for (int iter = 0; iter < NIT; iter++) {
        const int n0 = iter * 128;
        const bool has_next = (iter + 1 < NIT);
        if (has_next) scores_load_k(kbase, n0 + 128, tid, k_lo, k_hi);

        uint2 (*KFc)[8][33] = sm.KF[iter & 1];
        float acc[2][8][4] = {};
        #pragma unroll
        for (int kb = 0; kb < 8; kb++) {
            uint4 a[2];
            a[0] = sm.QF[wm * 2 + 0][kb][lane];
            a[1] = sm.QF[wm * 2 + 1][kb][lane];
            uint2 bfr[8];
            #pragma unroll
            for (int jn = 0; jn < 8; jn++) bfr[jn] = KFc[wn * 8 + jn][kb][lane];
            #pragma unroll
            for (int im = 0; im < 2; im++)
                #pragma unroll
                for (int jn = 0; jn < 8; jn++)
                    mma_tf32(acc[im][jn], (const uint32_t*)&a[im], (const uint32_t*)&bfr[jn]);
        }

        #pragma unroll
        for (int im = 0; im < 2; im++) {
            int mb = wm * 32 + im * 16;
            #pragma unroll
            for (int jn = 0; jn < 8; jn++) {
                int n = n0 + wn * 64 + jn * 8 + 2 * kq;
                float pu0 = ex2(acc[im][jn][0] * sc);
                float pu1 = ex2(acc[im][jn][1] * sc);
                float pu2 = ex2(acc[im][jn][2] * sc);
                float pu3 = ex2(acc[im][jn][3] * sc);
                l_acc[im][0] += pu0 + pu1;
                l_acc[im][1] += pu2 + pu3;
                *(float2*)&pstrip[(size_t)(mb + g) * SEQ + n]     = make_float2(pu0, pu1);
                *(float2*)&pstrip[(size_t)(mb + g + 8) * SEQ + n] = make_float2(pu2, pu3);
            }
        }

        if (has_next) scores_store_k(sm.KF[(iter + 1) & 1], tid, k_lo, k_hi);
        __syncthreads();
    }

    #pragma unroll
    for (int im = 0; im < 2; im++)
        #pragma unroll
        for (int rh = 0; rh < 2; rh++) {
            l_acc[im][rh] += __shfl_xor_sync(0xffffffff, l_acc[im][rh], 1);
            l_acc[im][rh] += __shfl_xor_sync(0xffffffff, l_acc[im][rh], 2);
        }
    if (kq == 0) {
        #pragma unroll
        for (int im = 0; im < 2; im++)
            #pragma unroll
            for (int rh = 0; rh < 2; rh++)
                sm.red[wn][wm * 32 + im * 16 + rh * 8 + g] = l_acc[im][rh];
    }
    __syncthreads();
    if (tid < 128) {
        float l = sm.red[0][tid] + sm.red[1][tid];
        invl_out[(size_t)bh * SEQ + m0 + tid] = 1.0f / l;
    }
}

// ---------------------------------------------------------------------------
// PV + normalization: ping-pong buffers, 2 CTAs/SM.
// ---------------------------------------------------------------------------
struct PvSmem {
    uint4 PF[2][8][4][33];
    uint2 VF[2][8][4][33];
    float sinvl[128];
};

__device__ __forceinline__ void pv_load_regs(
    const float* __restrict__ pbase, const float* __restrict__ vbase,
    int k0, int tid, float4* p_lo, float4* p_hi, float4& v_lo, float4& v_hi)
{
    #pragma unroll
    for (int i = 0; i < 2; i++) {
        int idx = tid + i * 256;
        int rp = idx >> 3, c4 = (idx & 7) * 4;
        const float* a0 = &pbase[(size_t)((rp >> 3) * 16 + (rp & 7)) * SEQ + k0 + c4];
        p_lo[i] = *(const float4*)a0;
        p_hi[i] = *(const float4*)(a0 + 8 * SEQ);
    }
    int rp = tid >> 4, c4 = (tid & 15) * 4;
    const float* v0 = &vbase[(size_t)(k0 + (rp >> 2) * 8 + (rp & 3)) * D_MODEL + c4];
    v_lo = *(const float4*)v0;
    v_hi = *(const float4*)(v0 + 4 * D_MODEL);
}

__device__ __forceinline__ void pv_store_smem(
    uint4 (*PF)[4][33], uint2 (*VF)[4][33], float* pbase, const float* sinvl,
    int k0, int tid, int write_p,
    const float4* p_lo, const float4* p_hi, const float4& v_lo, const float4& v_hi)
{
    #pragma unroll
    for (int i = 0; i < 2; i++) {
        int idx = tid + i * 256;
        int rp = idx >> 3, c4 = (idx & 7) * 4;
        int mt = rp >> 3, r8 = rp & 7;
        if (write_p) {
            float il0 = sinvl[mt * 16 + r8];
            float il1 = sinvl[mt * 16 + r8 + 8];
            float* a0 = &pbase[(size_t)(mt * 16 + r8) * SEQ + k0 + c4];
            *(float4*)a0 = make_float4(p_lo[i].x * il0, p_lo[i].y * il0,
                                       p_lo[i].z * il0, p_lo[i].w * il0);
            *(float4*)(a0 + 8 * SEQ) = make_float4(p_hi[i].x * il1, p_hi[i].y * il1,
                                                   p_hi[i].z * il1, p_hi[i].w * il1);
        }
        int kbk = c4 >> 3;
        int off = ((c4 >> 2) & 1) * 2;
        uint32_t* base = (uint32_t*)&PF[mt][kbk][r8 * 4];
        *(uint2*)&base[0 * 4 + off] = make_uint2(f2tf32(p_lo[i].x), f2tf32(p_hi[i].x));
        *(uint2*)&base[1 * 4 + off] = make_uint2(f2tf32(p_lo[i].y), f2tf32(p_hi[i].y));
        *(uint2*)&base[2 * 4 + off] = make_uint2(f2tf32(p_lo[i].z), f2tf32(p_hi[i].z));
        *(uint2*)&base[3 * 4 + off] = make_uint2(f2tf32(p_lo[i].w), f2tf32(p_hi[i].w));
    }
    {
        int rp = tid >> 4, c4 = (tid & 15) * 4;
        int kbk = rp >> 2, rq = rp & 3;
        int nt = c4 >> 3, gb = c4 & 7;
        VF[nt][kbk][(gb + 0) * 4 + rq] = make_uint2(f2tf32(v_lo.x), f2tf32(v_hi.x));
        VF[nt][kbk][(gb + 1) * 4 + rq] = make_uint2(f2tf32(v_lo.y), f2tf32(v_hi.y));
        VF[nt][kbk][(gb + 2) * 4 + rq] = make_uint2(f2tf32(v_lo.z), f2tf32(v_hi.z));
        VF[nt][kbk][(gb + 3) * 4 + rq] = make_uint2(f2tf32(v_lo.w), f2tf32(v_hi.w));
    }
}

__global__ void __launch_bounds__(256, 2)
pv_norm_tc(float* attn, const float* __restrict__ vb,
           const float* __restrict__ invl_in, float* __restrict__ ctx, int write_p)
{
    extern __shared__ char smem_raw[];
    PvSmem& sm = *(PvSmem*)smem_raw;

    const int tid  = threadIdx.x;
    const int warp = tid >> 5;
    const int lane = tid & 31;
    const int g    = lane >> 2;
    const int kq   = lane & 3;
    const int wm   = warp >> 1;
    const int wn   = warp & 1;

    const int bh = blockIdx.z;
    const int b  = bh >> 4;
    const int h  = bh & 15;
    const int m0 = blockIdx.x * 128;

    float* pbase = attn + ((size_t)bh * SEQ + m0) * SEQ;
    const float* vbase = vb + (size_t)b * SEQ * D_MODEL + h * HEADDIM;

    if (tid < 128) sm.sinvl[tid] = invl_in[(size_t)bh * SEQ + m0 + tid];
    __syncthreads();

    float acc[2][4][4] = {};
    float4 p_lo[2], p_hi[2], v_lo, v_hi;

    pv_load_regs(pbase, vbase, 0, tid, p_lo, p_hi, v_lo, v_hi);
    pv_store_smem(sm.PF[0], sm.VF[0], pbase, sm.sinvl, 0, tid, write_p,
                  p_lo, p_hi, v_lo, v_hi);
    __syncthreads();

    const int NT = SEQ / 32;
    for (int kt = 0; kt < NT; kt++) {
        const bool has_next = (kt + 1 < NT);
        if (has_next)
            pv_load_regs(pbase, vbase, (kt + 1) * 32, tid, p_lo, p_hi, v_lo, v_hi);

        uint4 (*PFc)[4][33] = sm.PF[kt & 1];
        uint2 (*VFc)[4][33] = sm.VF[kt & 1];
        #pragma unroll
        for (int kbk = 0; kbk < 4; kbk++) {
            uint4 a[2];
            a[0] = PFc[wm * 2 + 0][kbk][lane];
            a[1] = PFc[wm * 2 + 1][kbk][lane];
            uint2 bfr[4];
            #pragma unroll
            for (int jn = 0; jn < 4; jn++) bfr[jn] = VFc[wn * 4 + jn][kbk][lane];
            #pragma unroll
            for (int im = 0; im < 2; im++)
                #pragma unroll
                for (int jn = 0; jn < 4; jn++)
                    mma_tf32(acc[im][jn], (const uint32_t*)&a[im], (const uint32_t*)&bfr[jn]);
        }

        if (has_next)
            pv_store_smem(sm.PF[(kt + 1) & 1], sm.VF[(kt + 1) & 1], pbase, sm.sinvl,
                          (kt + 1) * 32, tid, write_p, p_lo, p_hi, v_lo, v_hi);
        __syncthreads();
    }

    #pragma unroll
    for (int im = 0; im < 2; im++) {
        int mr = wm * 32 + im * 16;
        float il0 = sm.sinvl[mr + g];
        float il1 = sm.sinvl[mr + g + 8];
        int mb = b * SEQ + m0 + mr;
        #pragma unroll
        for (int jn = 0; jn < 4; jn++) {
            int n = h * HEADDIM + wn * 32 + jn * 8 + 2 * kq;
            float* p0 = &ctx[(size_t)(mb + g) * D_MODEL + n];
            float* p1 = &ctx[(size_t)(mb + g + 8) * D_MODEL + n];
            p0[0] = acc[im][jn][0] * il0; p0[1] = acc[im][jn][1] * il0;
            p1[0] = acc[im][jn][2] * il1; p1[1] = acc[im][jn][3] * il1;
        }
    }
}

// ---------------------------------------------------------------------------
// Launch
// ---------------------------------------------------------------------------
extern "C" void kernel_launch(void* const* d_in, const int* in_sizes, int n_in,
                              void* d_out, int out_size)
{
    const float* Q     = (const float*)d_in[0];
    const float* Wq    = (const float*)d_in[1];
    const float* bq    = (const float*)d_in[2];
    const float* Wk    = (const float*)d_in[3];
    const float* bk    = (const float*)d_in[4];
    const float* Wv    = (const float*)d_in[5];
    const float* bv    = (const float*)d_in[6];
    const float* Wo    = (const float*)d_in[7];
    const float* bo    = (const float*)d_in[8];
    const float* scale = (const float*)d_in[9];

    const int M = in_sizes[0] / D_MODEL;
    const int B = M / SEQ;

    float* out = (float*)d_out;

    float *qp, *kp, *vp, *cp, *ap, *ilp;
    cudaGetSymbolAddress((void**)&qp, g_q);
    cudaGetSymbolAddress((void**)&kp, g_k);
    cudaGetSymbolAddress((void**)&vp, g_v);
    cudaGetSymbolAddress((void**)&cp, g_ctx);
    cudaGetSymbolAddress((void**)&ap, g_attn);
    cudaGetSymbolAddress((void**)&ilp, g_invl);

    const size_t out_elems = (size_t)M * D_MODEL;
    const int write_p = ((size_t)out_size > out_elems) ? 1 : 0;
    float* attn = write_p ? (out + out_elems) : ap;

    const int gemm_smem   = (int)(2 * sizeof(GemmSmem));
    const int scores_smem = (int)sizeof(ScoresSmem);
    const int pv_smem     = (int)sizeof(PvSmem);
    cudaFuncSetAttribute(qkv_proj_tc, cudaFuncAttributeMaxDynamicSharedMemorySize, gemm_smem);
    cudaFuncSetAttribute(gemm_bias_tc, cudaFuncAttributeMaxDynamicSharedMemorySize, gemm_smem);
    cudaFuncSetAttribute(scores_exp_tc, cudaFuncAttributeMaxDynamicSharedMemorySize, scores_smem);
    cudaFuncSetAttribute(pv_norm_tc, cudaFuncAttributeMaxDynamicSharedMemorySize, pv_smem);

    dim3 gqkv(D_MODEL / 128, M / 128, 3);
    qkv_proj_tc<<<gqkv, 256, gemm_smem>>>(Q, Wq, bq, Wk, bk, Wv, bv, qp, kp, vp);

    dim3 gsc(SEQ / 128, B * NHEADS);
    scores_exp_tc<<<gsc, 256, scores_smem>>>(qp, kp, scale, attn, ilp);

    dim3 gpv(SEQ / 128, 1, B * NHEADS);
    pv_norm_tc<<<gpv, 256, pv_smem>>>(attn, vp, ilp, cp, write_p);

    dim3 gproj(D_MODEL / 128, M / 128);
    gemm_bias_tc<<<gproj, 256, gemm_smem>>>(cp, Wo, bo, out);
}

// round 10
// speedup vs baseline: 3.0311x; 1.0189x over previous
#include <cuda_runtime.h>
#include <cuda_bf16.h>
#include <math.h>
#include <stdint.h>

#define D_MODEL 1024
#define SEQ     2048
#define NHEADS  16
#define HEADDIM 64
#define MAXB    2

// ---------------------------------------------------------------------------
// Device scratch
// ---------------------------------------------------------------------------
__device__ float g_q[MAXB * SEQ * D_MODEL];
__device__ float g_k[MAXB * SEQ * D_MODEL];
__device__ float g_v[MAXB * SEQ * D_MODEL];
__device__ float g_ctx[MAXB * SEQ * D_MODEL];
__device__ float g_invl[MAXB * NHEADS * SEQ];
__device__ float g_attn[(size_t)MAXB * NHEADS * SEQ * SEQ];

// ---------------------------------------------------------------------------
// tf32 helpers
// ---------------------------------------------------------------------------
__device__ __forceinline__ uint32_t f2tf32(float x) {
    uint32_t r;
    asm("cvt.rna.tf32.f32 %0, %1;" : "=r"(r) : "f"(x));
    return r;
}

__device__ __forceinline__ float ex2(float x) {
    float r;
    asm("ex2.approx.f32 %0, %1;" : "=f"(r) : "f"(x));
    return r;
}

__device__ __forceinline__ void mma_tf32(float* c, const uint32_t* a, const uint32_t* b) {
    asm("mma.sync.aligned.m16n8k8.row.col.f32.tf32.tf32.f32 "
        "{%0,%1,%2,%3}, {%4,%5,%6,%7}, {%8,%9}, {%0,%1,%2,%3};"
        : "+f"(c[0]), "+f"(c[1]), "+f"(c[2]), "+f"(c[3])
        : "r"(a[0]), "r"(a[1]), "r"(a[2]), "r"(a[3]), "r"(b[0]), "r"(b[1]));
}

// Write a uint2 fragment into half of a paired uint4 slot.
__device__ __forceinline__ void store_half4(uint4* slot, int half, uint2 v) {
    uint32_t* w = (uint32_t*)slot + half * 2;
    w[0] = v.x; w[1] = v.y;
}

// ---------------------------------------------------------------------------
// Projection GEMM: ping-pong SMEM + register staging, paired B frags
// ---------------------------------------------------------------------------
struct GemmSmem {
    uint4 AF[8][4][33];   // A frags: [mt][kb][lane]
    uint4 BF[8][4][33];   // paired B frags: [nt2][kb][lane] (.xy=2nt2, .zw=2nt2+1)
};

__device__ __forceinline__ void gemm_load_regs(
    const float* __restrict__ A, const float* __restrict__ W,
    int m0, int n0, int k0, int tid,
    float4* a_lo, float4* a_hi, float4* b_lo, float4* b_hi)
{
    #pragma unroll
    for (int i = 0; i < 2; i++) {
        int idx = tid + i * 256;
        int rp = idx >> 3, c4 = (idx & 7) * 4;
        const float* a0 = &A[(size_t)(m0 + (rp >> 3) * 16 + (rp & 7)) * D_MODEL + k0 + c4];
        a_lo[i] = *(const float4*)a0;
        a_hi[i] = *(const float4*)(a0 + 8 * D_MODEL);
        int rp2 = idx >> 5, c42 = (idx & 31) * 4;
        const float* b0 = &W[(size_t)(k0 + (rp2 >> 2) * 8 + (rp2 & 3)) * D_MODEL + n0 + c42];
        b_lo[i] = *(const float4*)b0;
        b_hi[i] = *(const float4*)(b0 + 4 * D_MODEL);
    }
}

__device__ __forceinline__ void gemm_store_smem(
    GemmSmem& s, int tid,
    const float4* a_lo, const float4* a_hi, const float4* b_lo, const float4* b_hi)
{
    #pragma unroll
    for (int i = 0; i < 2; i++) {
        int idx = tid + i * 256;
        int rp = idx >> 3, c4 = (idx & 7) * 4;
        int mt = rp >> 3, r8 = rp & 7;
        int kb  = c4 >> 3;
        int off = ((c4 >> 2) & 1) * 2;
        uint32_t* base = (uint32_t*)&s.AF[mt][kb][r8 * 4];
        *(uint2*)&base[0 * 4 + off] = make_uint2(f2tf32(a_lo[i].x), f2tf32(a_hi[i].x));
        *(uint2*)&base[1 * 4 + off] = make_uint2(f2tf32(a_lo[i].y), f2tf32(a_hi[i].y));
        *(uint2*)&base[2 * 4 + off] = make_uint2(f2tf32(a_lo[i].z), f2tf32(a_hi[i].z));
        *(uint2*)&base[3 * 4 + off] = make_uint2(f2tf32(a_lo[i].w), f2tf32(a_hi[i].w));
        int rp2 = idx >> 5, c42 = (idx & 31) * 4;
        int kb2 = rp2 >> 2, rq = rp2 & 3;
        int nt = c42 >> 3, gb = c42 & 7;
        int nt2 = nt >> 1, half = nt & 1;
        store_half4(&s.BF[nt2][kb2][(gb + 0) * 4 + rq], half,
                    make_uint2(f2tf32(b_lo[i].x), f2tf32(b_hi[i].x)));
        store_half4(&s.BF[nt2][kb2][(gb + 1) * 4 + rq], half,
                    make_uint2(f2tf32(b_lo[i].y), f2tf32(b_hi[i].y)));
        store_half4(&s.BF[nt2][kb2][(gb + 2) * 4 + rq], half,
                    make_uint2(f2tf32(b_lo[i].z), f2tf32(b_hi[i].z)));
        store_half4(&s.BF[nt2][kb2][(gb + 3) * 4 + rq], half,
                    make_uint2(f2tf32(b_lo[i].w), f2tf32(b_hi[i].w)));
    }
}

__device__ __forceinline__ void gemm_body(
    GemmSmem* bufs, const float* __restrict__ A, const float* __restrict__ W,
    const float* __restrict__ bias, float* __restrict__ C, int m0, int n0)
{
    const int tid  = threadIdx.x;
    const int warp = tid >> 5;
    const int lane = tid & 31;
    const int g    = lane >> 2;
    const int kq   = lane & 3;
    const int wm   = warp >> 1;
    const int wn   = warp & 1;

    float acc[2][8][4] = {};
    float4 a_lo[2], a_hi[2], b_lo[2], b_hi[2];

    gemm_load_regs(A, W, m0, n0, 0, tid, a_lo, a_hi, b_lo, b_hi);
    gemm_store_smem(bufs[0], tid, a_lo, a_hi, b_lo, b_hi);
    __syncthreads();

    const int NT = D_MODEL / 32;
    for (int kt = 0; kt < NT; kt++) {
        GemmSmem& cur = bufs[kt & 1];
        const bool has_next = (kt + 1 < NT);
        if (has_next)
            gemm_load_regs(A, W, m0, n0, (kt + 1) * 32, tid, a_lo, a_hi, b_lo, b_hi);

        #pragma unroll
        for (int kb = 0; kb < 4; kb++) {
            uint4 a[2];
            a[0] = cur.AF[wm * 2 + 0][kb][lane];
            a[1] = cur.AF[wm * 2 + 1][kb][lane];
            #pragma unroll
            for (int jn2 = 0; jn2 < 4; jn2++) {
                uint4 b2 = cur.BF[wn * 4 + jn2][kb][lane];
                #pragma unroll
                for (int im = 0; im < 2; im++) {
                    mma_tf32(acc[im][2 * jn2 + 0], (const uint32_t*)&a[im], (const uint32_t*)&b2.x);
                    mma_tf32(acc[im][2 * jn2 + 1], (const uint32_t*)&a[im], (const uint32_t*)&b2.z);
                }
            }
        }

        if (has_next)
            gemm_store_smem(bufs[(kt + 1) & 1], tid, a_lo, a_hi, b_lo, b_hi);
        __syncthreads();
    }

    #pragma unroll
    for (int im = 0; im < 2; im++) {
        int mb = m0 + wm * 32 + im * 16;
        #pragma unroll
        for (int jn = 0; jn < 8; jn++) {
            int n = n0 + wn * 64 + jn * 8 + 2 * kq;
            float b0 = bias[n], b1 = bias[n + 1];
            float* p0 = &C[(size_t)(mb + g) * D_MODEL + n];
            float* p1 = &C[(size_t)(mb + g + 8) * D_MODEL + n];
            p0[0] = acc[im][jn][0] + b0; p0[1] = acc[im][jn][1] + b1;
            p1[0] = acc[im][jn][2] + b0; p1[1] = acc[im][jn][3] + b1;
        }
    }
}

__global__ void __launch_bounds__(256, 2)
qkv_proj_tc(const float* __restrict__ A,
            const float* __restrict__ Wq, const float* __restrict__ bq,
            const float* __restrict__ Wk, const float* __restrict__ bk,
            const float* __restrict__ Wv, const float* __restrict__ bv,
            float* __restrict__ oq, float* __restrict__ ok, float* __restrict__ ov)
{
    extern __shared__ char smem_raw[];
    GemmSmem* bufs = (GemmSmem*)smem_raw;
    const int z = blockIdx.z;
    const float* W    = (z == 0) ? Wq : (z == 1) ? Wk : Wv;
    const float* bias = (z == 0) ? bq : (z == 1) ? bk : bv;
    float*       C    = (z == 0) ? oq : (z == 1) ? ok : ov;
    gemm_body(bufs, A, W, bias, C, blockIdx.y * 128, blockIdx.x * 128);
}

__global__ void __launch_bounds__(256, 2)
gemm_bias_tc(const float* __restrict__ A, const float* __restrict__ W,
             const float* __restrict__ bias, float* __restrict__ C)
{
    extern __shared__ char smem_raw[];
    GemmSmem* bufs = (GemmSmem*)smem_raw;
    gemm_body(bufs, A, W, bias, C, blockIdx.y * 128, blockIdx.x * 128);
}

// ---------------------------------------------------------------------------
// scores+exp fused: ping-pong K (paired frags); CTA = 128-row strip x 2048 keys
// ---------------------------------------------------------------------------
struct ScoresSmem {
    uint4 QF[8][8][33];       // Q A-frags
    uint4 KF[2][8][8][33];    // paired K B-frags: [buf][nt2][kb][lane]
    float red[2][128];
};

__device__ __forceinline__ void scores_load_k(
    const float* __restrict__ kbase, int n0, int tid, float4* k_lo, float4* k_hi)
{
    #pragma unroll
    for (int i = 0; i < 4; i++) {
        int idx = tid + i * 256;
        int n  = idx >> 3;
        int c8 = (idx & 7) * 8;
        const float* p = &kbase[(size_t)(n0 + n) * D_MODEL + c8];
        k_lo[i] = *(const float4*)p;
        k_hi[i] = *(const float4*)(p + 4);
    }
}

__device__ __forceinline__ void scores_store_k(
    uint4 (*KF)[8][33], int tid, const float4* k_lo, const float4* k_hi)
{
    #pragma unroll
    for (int i = 0; i < 4; i++) {
        int idx = tid + i * 256;
        int n  = idx >> 3;
        int c8 = (idx & 7) * 8;
        int nt  = n >> 3;
        int gg  = n & 7;
        int kbk = c8 >> 3;
        int nt2 = nt >> 1, half = nt & 1;
        store_half4(&KF[nt2][kbk][gg * 4 + 0], half, make_uint2(f2tf32(k_lo[i].x), f2tf32(k_hi[i].x)));
        store_half4(&KF[nt2][kbk][gg * 4 + 1], half, make_uint2(f2tf32(k_lo[i].y), f2tf32(k_hi[i].y)));
        store_half4(&KF[nt2][kbk][gg * 4 + 2], half, make_uint2(f2tf32(k_lo[i].z), f2tf32(k_hi[i].z)));
        store_half4(&KF[nt2][kbk][gg * 4 + 3], half, make_uint2(f2tf32(k_lo[i].w), f2tf32(k_hi[i].w)));
    }
}

__global__ void __launch_bounds__(256, 2)
scores_exp_tc(const float* __restrict__ qb, const float* __restrict__ kb_,
              const float* __restrict__ scale_ptr, float* __restrict__ attn,
              float* __restrict__ invl_out)
{
    extern __shared__ char smem_raw[];
    ScoresSmem& sm = *(ScoresSmem*)smem_raw;

    const int tid  = threadIdx.x;
    const int warp = tid >> 5;
    const int lane = tid & 31;
    const int g    = lane >> 2;
    const int kq   = lane & 3;
    const int wm   = warp >> 1;
    const int wn   = warp & 1;

    const int bh = blockIdx.y;
    const int b  = bh >> 4;
    const int h  = bh & 15;
    const int m0 = blockIdx.x * 128;

    const float sc = scale_ptr[0] * 1.44269504088896f;

    const float* qbase = qb  + (size_t)(b * SEQ + m0) * D_MODEL + h * HEADDIM;
    const float* kbase = kb_ + (size_t)b * SEQ * D_MODEL + h * HEADDIM;
    float* pstrip = attn + ((size_t)bh * SEQ + m0) * SEQ;

    // ---- Q strip 128x64 -> QF (once) ----
    #pragma unroll
    for (int k0 = 0; k0 < 64; k0 += 32) {
        #pragma unroll
        for (int i = 0; i < 2; i++) {
            int idx = tid + i * 256;
            int rp = idx >> 3;
            int c4 = (idx & 7) * 4;
            int mt = rp >> 3;
            int r8 = rp & 7;
            const float* a0 = &qbase[(size_t)(mt * 16 + r8) * D_MODEL + k0 + c4];
            float4 vlo = *(const float4*)a0;
            float4 vhi = *(const float4*)(a0 + 8 * D_MODEL);
            int kb  = (k0 + c4) >> 3;
            int off = ((c4 >> 2) & 1) * 2;
            uint32_t* base = (uint32_t*)&sm.QF[mt][kb][r8 * 4];
            *(uint2*)&base[0 * 4 + off] = make_uint2(f2tf32(vlo.x), f2tf32(vhi.x));
            *(uint2*)&base[1 * 4 + off] = make_uint2(f2tf32(vlo.y), f2tf32(vhi.y));
            *(uint2*)&base[2 * 4 + off] = make_uint2(f2tf32(vlo.z), f2tf32(vhi.z));
            *(uint2*)&base[3 * 4 + off] = make_uint2(f2tf32(vlo.w), f2tf32(vhi.w));
        }
    }

    float l_acc[2][2] = {};
    float4 k_lo[4], k_hi[4];

    scores_load_k(kbase, 0, tid, k_lo, k_hi);
    scores_store_k(sm.KF[0], tid, k_lo, k_hi);
    __syncthreads();

    const int NIT = SEQ / 128;
    for (int iter = 0; iter < NIT; iter++) {
        const int n0 = iter * 128;
        const bool has_next = (iter + 1 < NIT);
        if (has_next) scores_load_k(kbase, n0 + 128, tid, k_lo, k_hi);

        uint4 (*KFc)[8][33] = sm.KF[iter & 1];
        float acc[2][8][4] = {};
        #pragma unroll
        for (int kb = 0; kb < 8; kb++) {
            uint4 a[2];
            a[0] = sm.QF[wm * 2 + 0][kb][lane];
            a[1] = sm.QF[wm * 2 + 1][kb][lane];
            #pragma unroll
            for (int jn2 = 0; jn2 < 4; jn2++) {
                uint4 kf = KFc[wn * 4 + jn2][kb][lane];
                #pragma unroll
                for (int im = 0; im < 2; im++) {
                    mma_tf32(acc[im][2 * jn2 + 0], (const uint32_t*)&a[im], (const uint32_t*)&kf.x);
                    mma_tf32(acc[im][2 * jn2 + 1], (const uint32_t*)&a[im], (const uint32_t*)&kf.z);
                }
            }
        }

        #pragma unroll
        for (int im = 0; im < 2; im++) {
            int mb = wm * 32 + im * 16;
            #pragma unroll
            for (int jn = 0; jn < 8; jn++) {
                int n = n0 + wn * 64 + jn * 8 + 2 * kq;
                float pu0 = ex2(acc[im][jn][0] * sc);
                float pu1 = ex2(acc[im][jn][1] * sc);
                float pu2 = ex2(acc[im][jn][2] * sc);
                float pu3 = ex2(acc[im][jn][3] * sc);
                l_acc[im][0] += pu0 + pu1;
                l_acc[im][1] += pu2 + pu3;
                *(float2*)&pstrip[(size_t)(mb + g) * SEQ + n]     = make_float2(pu0, pu1);
                *(float2*)&pstrip[(size_t)(mb + g + 8) * SEQ + n] = make_float2(pu2, pu3);
            }
        }

        if (has_next) scores_store_k(sm.KF[(iter + 1) & 1], tid, k_lo, k_hi);
        __syncthreads();
    }

    #pragma unroll
    for (int im = 0; im < 2; im++)
        #pragma unroll
        for (int rh = 0; rh < 2; rh++) {
            l_acc[im][rh] += __shfl_xor_sync(0xffffffff, l_acc[im][rh], 1);
            l_acc[im][rh] += __shfl_xor_sync(0xffffffff, l_acc[im][rh], 2);
        }
    if (kq == 0) {
        #pragma unroll
        for (int im = 0; im < 2; im++)
            #pragma unroll
            for (int rh = 0; rh < 2; rh++)
                sm.red[wn][wm * 32 + im * 16 + rh * 8 + g] = l_acc[im][rh];
    }
    __syncthreads();
    if (tid < 128) {
        float l = sm.red[0][tid] + sm.red[1][tid];
        invl_out[(size_t)bh * SEQ + m0 + tid] = 1.0f / l;
    }
}

// ---------------------------------------------------------------------------
// PV + normalization: ping-pong buffers, paired V frags
// ---------------------------------------------------------------------------
struct PvSmem {
    uint4 PF[2][8][4][33];    // P A-frags
    uint4 VF[2][4][4][33];    // paired V B-frags: [buf][nt2][kb][lane]
    float sinvl[128];
};

__device__ __forceinline__ void pv_load_regs(
    const float* __restrict__ pbase, const float* __restrict__ vbase,
    int k0, int tid, float4* p_lo, float4* p_hi, float4& v_lo, float4& v_hi)
{
    #pragma unroll
    for (int i = 0; i < 2; i++) {
        int idx = tid + i * 256;
        int rp = idx >> 3, c4 = (idx & 7) * 4;
        const float* a0 = &pbase[(size_t)((rp >> 3) * 16 + (rp & 7)) * SEQ + k0 + c4];
        p_lo[i] = *(const float4*)a0;
        p_hi[i] = *(const float4*)(a0 + 8 * SEQ);
    }
    int rp = tid >> 4, c4 = (tid & 15) * 4;
    const float* v0 = &vbase[(size_t)(k0 + (rp >> 2) * 8 + (rp & 3)) * D_MODEL + c4];
    v_lo = *(const float4*)v0;
    v_hi = *(const float4*)(v0 + 4 * D_MODEL);
}

__device__ __forceinline__ void pv_store_smem(
    uint4 (*PF)[4][33], uint4 (*VF)[4][33], float* pbase, const float* sinvl,
    int k0, int tid, int write_p,
    const float4* p_lo, const float4* p_hi, const float4& v_lo, const float4& v_hi)
{
    #pragma unroll
    for (int i = 0; i < 2; i++) {
        int idx = tid + i * 256;
        int rp = idx >> 3, c4 = (idx & 7) * 4;
        int mt = rp >> 3, r8 = rp & 7;
        if (write_p) {
            float il0 = sinvl[mt * 16 + r8];
            float il1 = sinvl[mt * 16 + r8 + 8];
            float* a0 = &pbase[(size_t)(mt * 16 + r8) * SEQ + k0 + c4];
            *(float4*)a0 = make_float4(p_lo[i].x * il0, p_lo[i].y * il0,
                                       p_lo[i].z * il0, p_lo[i].w * il0);
            *(float4*)(a0 + 8 * SEQ) = make_float4(p_hi[i].x * il1, p_hi[i].y * il1,
                                                   p_hi[i].z * il1, p_hi[i].w * il1);
        }
        int kbk = c4 >> 3;
        int off = ((c4 >> 2) & 1) * 2;
        uint32_t* base = (uint32_t*)&PF[mt][kbk][r8 * 4];
        *(uint2*)&base[0 * 4 + off] = make_uint2(f2tf32(p_lo[i].x), f2tf32(p_hi[i].x));
        *(uint2*)&base[1 * 4 + off] = make_uint2(f2tf32(p_lo[i].y), f2tf32(p_hi[i].y));
        *(uint2*)&base[2 * 4 + off] = make_uint2(f2tf32(p_lo[i].z), f2tf32(p_hi[i].z));
        *(uint2*)&base[3 * 4 + off] = make_uint2(f2tf32(p_lo[i].w), f2tf32(p_hi[i].w));
    }
    {
        int rp = tid >> 4, c4 = (tid & 15) * 4;
        int kbk = rp >> 2, rq = rp & 3;
        int nt = c4 >> 3, gb = c4 & 7;
        int nt2 = nt >> 1, half = nt & 1;
        store_half4(&VF[nt2][kbk][(gb + 0) * 4 + rq], half, make_uint2(f2tf32(v_lo.x), f2tf32(v_hi.x)));
        store_half4(&VF[nt2][kbk][(gb + 1) * 4 + rq], half, make_uint2(f2tf32(v_lo.y), f2tf32(v_hi.y)));
        store_half4(&VF[nt2][kbk][(gb + 2) * 4 + rq], half, make_uint2(f2tf32(v_lo.z), f2tf32(v_hi.z)));
        store_half4(&VF[nt2][kbk][(gb + 3) * 4 + rq], half, make_uint2(f2tf32(v_lo.w), f2tf32(v_hi.w)));
    }
}

__global__ void __launch_bounds__(256, 2)
pv_norm_tc(float* attn, const float* __restrict__ vb,
           const float* __restrict__ invl_in, float* __restrict__ ctx, int write_p)
{
    extern __shared__ char smem_raw[];
    PvSmem& sm = *(PvSmem*)smem_raw;

    const int tid  = threadIdx.x;
    const int warp = tid >> 5;
    const int lane = tid & 31;
    const int g    = lane >> 2;
    const int kq   = lane & 3;
    const int wm   = warp >> 1;
    const int wn   = warp & 1;

    const int bh = blockIdx.z;
    const int b  = bh >> 4;
    const int h  = bh & 15;
    const int m0 = blockIdx.x * 128;

    float* pbase = attn + ((size_t)bh * SEQ + m0) * SEQ;
    const float* vbase = vb + (size_t)b * SEQ * D_MODEL + h * HEADDIM;

    if (tid < 128) sm.sinvl[tid] = invl_in[(size_t)bh * SEQ + m0 + tid];
    __syncthreads();

    float acc[2][4][4] = {};
    float4 p_lo[2], p_hi[2], v_lo, v_hi;

    pv_load_regs(pbase, vbase, 0, tid, p_lo, p_hi, v_lo, v_hi);
    pv_store_smem(sm.PF[0], sm.VF[0], pbase, sm.sinvl, 0, tid, write_p,
                  p_lo, p_hi, v_lo, v_hi);
    __syncthreads();

    const int NT = SEQ / 32;
    for (int kt = 0; kt < NT; kt++) {
        const bool has_next = (kt + 1 < NT);
        if (has_next)
            pv_load_regs(pbase, vbase, (kt + 1) * 32, tid, p_lo, p_hi, v_lo, v_hi);

        uint4 (*PFc)[4][33] = sm.PF[kt & 1];
        uint4 (*VFc)[4][33] = sm.VF[kt & 1];
        #pragma unroll
        for (int kbk = 0; kbk < 4; kbk++) {
            uint4 a[2];
            a[0] = PFc[wm * 2 + 0][kbk][lane];
            a[1] = PFc[wm * 2 + 1][kbk][lane];
            #pragma unroll
            for (int jn2 = 0; jn2 < 2; jn2++) {
                uint4 vf = VFc[wn * 2 + jn2][kbk][lane];
                #pragma unroll
                for (int im = 0; im < 2; im++) {
                    mma_tf32(acc[im][2 * jn2 + 0], (const uint32_t*)&a[im], (const uint32_t*)&vf.x);
                    mma_tf32(acc[im][2 * jn2 + 1], (const uint32_t*)&a[im], (const uint32_t*)&vf.z);
                }
            }
        }

        if (has_next)
            pv_store_smem(sm.PF[(kt + 1) & 1], sm.VF[(kt + 1) & 1], pbase, sm.sinvl,
                          (kt + 1) * 32, tid, write_p, p_lo, p_hi, v_lo, v_hi);
        __syncthreads();
    }

    #pragma unroll
    for (int im = 0; im < 2; im++) {
        int mr = wm * 32 + im * 16;
        float il0 = sm.sinvl[mr + g];
        float il1 = sm.sinvl[mr + g + 8];
        int mb = b * SEQ + m0 + mr;
        #pragma unroll
        for (int jn = 0; jn < 4; jn++) {
            int n = h * HEADDIM + wn * 32 + jn * 8 + 2 * kq;
            float* p0 = &ctx[(size_t)(mb + g) * D_MODEL + n];
            float* p1 = &ctx[(size_t)(mb + g + 8) * D_MODEL + n];
            p0[0] = acc[im][jn][0] * il0; p0[1] = acc[im][jn][1] * il0;
            p1[0] = acc[im][jn][2] * il1; p1[1] = acc[im][jn][3] * il1;
        }
    }
}

// ---------------------------------------------------------------------------
// Launch
// ---------------------------------------------------------------------------
extern "C" void kernel_launch(void* const* d_in, const int* in_sizes, int n_in,
                              void* d_out, int out_size)
{
    const float* Q     = (const float*)d_in[0];
    const float* Wq    = (const float*)d_in[1];
    const float* bq    = (const float*)d_in[2];
    const float* Wk    = (const float*)d_in[3];
    const float* bk    = (const float*)d_in[4];
    const float* Wv    = (const float*)d_in[5];
    const float* bv    = (const float*)d_in[6];
    const float* Wo    = (const float*)d_in[7];
    const float* bo    = (const float*)d_in[8];
    const float* scale = (const float*)d_in[9];

    const int M = in_sizes[0] / D_MODEL;
    const int B = M / SEQ;

    float* out = (float*)d_out;

    float *qp, *kp, *vp, *cp, *ap, *ilp;
    cudaGetSymbolAddress((void**)&qp, g_q);
    cudaGetSymbolAddress((void**)&kp, g_k);
    cudaGetSymbolAddress((void**)&vp, g_v);
    cudaGetSymbolAddress((void**)&cp, g_ctx);
    cudaGetSymbolAddress((void**)&ap, g_attn);
    cudaGetSymbolAddress((void**)&ilp, g_invl);

    const size_t out_elems = (size_t)M * D_MODEL;
    const int write_p = ((size_t)out_size > out_elems) ? 1 : 0;
    float* attn = write_p ? (out + out_elems) : ap;

    const int gemm_smem   = (int)(2 * sizeof(GemmSmem));
    const int scores_smem = (int)sizeof(ScoresSmem);
    const int pv_smem     = (int)sizeof(PvSmem);
    cudaFuncSetAttribute(qkv_proj_tc, cudaFuncAttributeMaxDynamicSharedMemorySize, gemm_smem);
    cudaFuncSetAttribute(gemm_bias_tc, cudaFuncAttributeMaxDynamicSharedMemorySize, gemm_smem);
    cudaFuncSetAttribute(scores_exp_tc, cudaFuncAttributeMaxDynamicSharedMemorySize, scores_smem);
    cudaFuncSetAttribute(pv_norm_tc, cudaFuncAttributeMaxDynamicSharedMemorySize, pv_smem);

    dim3 gqkv(D_MODEL / 128, M / 128, 3);
    qkv_proj_tc<<<gqkv, 256, gemm_smem>>>(Q, Wq, bq, Wk, bk, Wv, bv, qp, kp, vp);

    dim3 gsc(SEQ / 128, B * NHEADS);
    scores_exp_tc<<<gsc, 256, scores_smem>>>(qp, kp, scale, attn, ilp);

    dim3 gpv(SEQ / 128, 1, B * NHEADS);
    pv_norm_tc<<<gpv, 256, pv_smem>>>(attn, vp, ilp, cp, write_p);

    dim3 gproj(D_MODEL / 128, M / 128);
    gemm_bias_tc<<<gproj, 256, gemm_smem>>>(cp, Wo, bo, out);
}